// round 14
// baseline (speedup 1.0000x reference)
#include <cuda_runtime.h>
#include <cuda_fp16.h>
#include <math.h>
#include <stdint.h>

#define TT 100
#define BB 128
#define HH 512
#define GG 2048            // 4*H
#define NIN 128            // rnn input dim
#define NITEMS 10000
#define KL 544             // H + SDIM
#define NPN 128000000      // TT*BB*NITEMS
#define KP 576             // K padded (row stride for split buffers)
#define NP 10240           // items padded to 40*256

// HMMA GEMM config for final linear (fp16 split-A, single-B, 17 K-stages x 2 A-passes)
#define LIN_STAGES 17      // 544/32
#define LDS_PAD 40         // 32 data + 8 pad halves per smem row

// persistent LSTM config
#define LSTM_CTAS 128
#define HS_STRIDE 66       // h_s k-row stride: EVEN (f32x2 pair alignment)

typedef unsigned long long ull;

// ---------------- static device scratch (no runtime allocation) ----------------
__device__ float g_ars[TT * BB * NIN];
__device__ float g_xproj[TT * BB * GG];
__device__ float g_h[2][BB * HH];
__device__ float g_l2[2];
__device__ unsigned g_barrier;
__device__ __half g_Ah[(size_t)TT * BB * KP];   // fp16 hi(A)
__device__ __half g_Al[(size_t)TT * BB * KP];   // fp16 lo(A)
__device__ __half g_B[(size_t)NP * KP];         // fp16 W_lin (single copy)

// ---------------- f32x2 helpers ----------------
__device__ __forceinline__ ull pack2(float x, float y) {
    ull v; asm("mov.b64 %0,{%1,%2};" : "=l"(v) : "f"(x), "f"(y)); return v;
}
__device__ __forceinline__ float2 unpack2(ull v) {
    float2 f; asm("mov.b64 {%0,%1},%2;" : "=f"(f.x), "=f"(f.y) : "l"(v)); return f;
}
__device__ __forceinline__ void fma2(ull &c, ull a, ull b) {
    asm("fma.rn.f32x2 %0,%1,%2,%3;" : "=l"(c) : "l"(a), "l"(b), "l"(c));
}
__device__ __forceinline__ float sigf(float x) { return 1.0f / (1.0f + expf(-x)); }

__device__ __forceinline__ uint32_t smem_u32(const void* p) {
    uint32_t a;
    asm("{ .reg .u64 t; cvta.to.shared.u64 t, %1; cvt.u32.u64 %0, t; }" : "=r"(a) : "l"(p));
    return a;
}

// ---------------- cp.async / ldmatrix / mma (baseline sm_80 PTX) ----------------
#define CP_ASYNC16(sdst, gsrc) \
    asm volatile("cp.async.cg.shared.global [%0], [%1], 16;" :: "r"(sdst), "l"(gsrc))
#define CP_COMMIT() asm volatile("cp.async.commit_group;" ::: "memory")
#define CP_WAIT(n)  asm volatile("cp.async.wait_group %0;" :: "n"(n) : "memory")

#define LDSM_X4(r0, r1, r2, r3, addr) \
    asm volatile("ldmatrix.sync.aligned.m8n8.x4.shared.b16 {%0,%1,%2,%3}, [%4];" \
        : "=r"(r0), "=r"(r1), "=r"(r2), "=r"(r3) : "r"(addr))

#define MMA16816H(c0, c1, c2, c3, a0, a1, a2, a3, b0, b1) \
    asm volatile("mma.sync.aligned.m16n8k16.row.col.f32.f16.f16.f32 " \
        "{%0,%1,%2,%3}, {%4,%5,%6,%7}, {%8,%9}, {%0,%1,%2,%3};" \
        : "+f"(c0), "+f"(c1), "+f"(c2), "+f"(c3) \
        : "r"(a0), "r"(a1), "r"(a2), "r"(a3), "r"(b0), "r"(b1))

// ================= init (also resets grid barrier each replay) =================
__global__ void k_init(const float* __restrict__ hx) {
    int i = blockIdx.x * blockDim.x + threadIdx.x;
    if (i < BB * HH) g_h[0][i] = hx[i];
    if (i == 0) g_barrier = 0u;
}

// ================= build ars =================
__global__ void k_ars(const int* __restrict__ act, const float* __restrict__ rew,
                      const float* __restrict__ stat, const float* __restrict__ emb) {
    int idx = blockIdx.x * blockDim.x + threadIdx.x;
    if (idx >= TT * BB * 32) return;
    int tb = idx >> 5;
    int k = (idx & 31) * 4;
    float4 v;
    if (k < 64) {
        v = *(const float4*)&emb[(size_t)act[tb] * 64 + k];
    } else if (k < 96) {
        float r = rew[tb];
        int ri = (int)floorf((32.0f * (2.0f - r)) / 4.0f);
        int kb = k - 64;
        v.x = (ri == kb    ) ? 1.f : 0.f;
        v.y = (ri == kb + 1) ? 1.f : 0.f;
        v.z = (ri == kb + 2) ? 1.f : 0.f;
        v.w = (ri == kb + 3) ? 1.f : 0.f;
    } else {
        v = *(const float4*)&stat[(size_t)tb * 32 + (k - 96)];
    }
    *(float4*)&g_ars[(size_t)tb * NIN + k] = v;
}

// ================= statsplit: A cols 512..543 = fp16 split(stat) =================
__global__ void k_statsplit(const float* __restrict__ stat) {
    int idx = blockIdx.x * blockDim.x + threadIdx.x;   // over 12800*32
    if (idx >= TT * BB * 32) return;
    int tb = idx >> 5, s = idx & 31;
    float v = stat[(size_t)tb * 32 + s];
    __half hh = __float2half(v);
    __half hl = __float2half(v - __half2float(hh));
    size_t o = (size_t)tb * KP + HH + s;
    g_Ah[o] = hh;
    g_Al[o] = hl;
}

// ================= x_proj (unchanged, known passing) ==================
__global__ __launch_bounds__(256, 2) void k_xproj(
    const float* __restrict__ W_ih, const float* __restrict__ b_ih,
    const float* __restrict__ b_hh)
{
    __shared__ __align__(16) float A_s[8][132];
    __shared__ __align__(16) float B2_s[8][264];
    const int tid = threadIdx.x;
    const int g0  = blockIdx.x * 128;
    const int tb0 = blockIdx.y * 128;
    const int tx = tid & 15;
    const int ty = tid >> 4;
    const int mf = tid >> 1;
    const int kf = (tid & 1) * 4;

    ull acc[4][8];
    #pragma unroll
    for (int i = 0; i < 4; i++)
        #pragma unroll
        for (int j = 0; j < 8; j++) acc[i][j] = 0ull;

    float4 rA = *(const float4*)&g_ars[(size_t)(tb0 + mf) * NIN + kf];
    float4 rB = *(const float4*)&W_ih[(size_t)(g0 + mf) * NIN + kf];

    for (int kt = 0; kt < NIN / 8; kt++) {
        A_s[kf + 0][mf] = rA.x; A_s[kf + 1][mf] = rA.y;
        A_s[kf + 2][mf] = rA.z; A_s[kf + 3][mf] = rA.w;
        *(ull*)&B2_s[kf + 0][2 * mf] = pack2(rB.x, rB.x);
        *(ull*)&B2_s[kf + 1][2 * mf] = pack2(rB.y, rB.y);
        *(ull*)&B2_s[kf + 2][2 * mf] = pack2(rB.z, rB.z);
        *(ull*)&B2_s[kf + 3][2 * mf] = pack2(rB.w, rB.w);
        __syncthreads();
        if (kt + 1 < NIN / 8) {
            int k0n = (kt + 1) * 8;
            rA = *(const float4*)&g_ars[(size_t)(tb0 + mf) * NIN + k0n + kf];
            rB = *(const float4*)&W_ih[(size_t)(g0 + mf) * NIN + k0n + kf];
        }
        #pragma unroll
        for (int k = 0; k < 8; k++) {
            ulonglong2 a01 = *(const ulonglong2*)&A_s[k][tx * 8];
            ulonglong2 a23 = *(const ulonglong2*)&A_s[k][tx * 8 + 4];
            ull a[4] = {a01.x, a01.y, a23.x, a23.y};
            #pragma unroll
            for (int jh = 0; jh < 2; jh++) {
                ulonglong2 b01 = *(const ulonglong2*)&B2_s[k][ty * 16 + jh * 8];
                ulonglong2 b23 = *(const ulonglong2*)&B2_s[k][ty * 16 + jh * 8 + 4];
                ull b[4] = {b01.x, b01.y, b23.x, b23.y};
                #pragma unroll
                for (int i = 0; i < 4; i++)
                    #pragma unroll
                    for (int j = 0; j < 4; j++)
                        fma2(acc[i][jh * 4 + j], a[i], b[j]);
            }
        }
        __syncthreads();
    }
    float bs[8];
    #pragma unroll
    for (int j = 0; j < 8; j++) {
        int g = g0 + ty * 8 + j;
        bs[j] = b_ih[g] + b_hh[g];
    }
    #pragma unroll
    for (int rp = 0; rp < 4; rp++) {
        float lo[8], hi[8];
        #pragma unroll
        for (int j = 0; j < 8; j++) {
            float2 c = unpack2(acc[rp][j]);
            lo[j] = c.x + bs[j]; hi[j] = c.y + bs[j];
        }
        int row = tb0 + tx * 8 + rp * 2;
        size_t o0 = (size_t)row * GG + g0 + ty * 8;
        *(float4*)&g_xproj[o0]          = make_float4(lo[0], lo[1], lo[2], lo[3]);
        *(float4*)&g_xproj[o0 + 4]      = make_float4(lo[4], lo[5], lo[6], lo[7]);
        *(float4*)&g_xproj[o0 + GG]     = make_float4(hi[0], hi[1], hi[2], hi[3]);
        *(float4*)&g_xproj[o0 + GG + 4] = make_float4(hi[4], hi[5], hi[6], hi[7]);
    }
}

// ================= persistent LSTM (pipelined; unchanged except fp16 h writes) ==
#define LP_WD_SZ   (512 * 64)
#define LP_HS_OFF  LP_WD_SZ
#define LP_HS_SZ   (32 * HS_STRIDE)
#define LP_GS_OFF  (LP_HS_OFF + 2 * LP_HS_SZ + 2)
#define LP_SM_FLOATS (LP_GS_OFF + 64 * 33 + 4)

__global__ __launch_bounds__(256) void k_lstm_persist(
    const float* __restrict__ W_hh, const float* __restrict__ cx)
{
    extern __shared__ __align__(16) float smf[];
    float* Wd   = smf;
    float* h_sb = smf + LP_HS_OFF;
    float* gs   = smf + LP_GS_OFF;

    const int tid = threadIdx.x;
    const int m0 = blockIdx.x * 8;
    const int r0 = blockIdx.y * 64;
    const int tx = tid & 15;
    const int ty = tid >> 4;
    const int lr  = tid >> 3,  lk4  = tid & 7;
    const int lr2 = (tid + 256) >> 3, lk42 = tid & 7;

    #pragma unroll
    for (int it = 0; it < 16; it++) {
        int idx = tid + it * 256;
        int c = idx >> 7;
        int k4 = idx & 127;
        int grow = (c >> 3) * HH + m0 + (c & 7);
        float4 v = *(const float4*)&W_hh[(size_t)grow * HH + k4 * 4];
        *(ull*)&Wd[(size_t)(k4 * 4 + 0) * 64 + 2 * c] = pack2(v.x, v.x);
        *(ull*)&Wd[(size_t)(k4 * 4 + 1) * 64 + 2 * c] = pack2(v.y, v.y);
        *(ull*)&Wd[(size_t)(k4 * 4 + 2) * 64 + 2 * c] = pack2(v.z, v.z);
        *(ull*)&Wd[(size_t)(k4 * 4 + 3) * 64 + 2 * c] = pack2(v.w, v.w);
    }

    float creg[2];
    #pragma unroll
    for (int e = 0; e < 2; e++) {
        int p = tid * 2 + e;
        creg[e] = cx[(size_t)(r0 + (p >> 3)) * HH + m0 + (p & 7)];
    }

    const int c0 = 2 * ty, c1 = 2 * ty + 1;
    const int gcol0 = (c0 >> 3) * HH + m0 + (c0 & 7);
    const int gcol1 = (c1 >> 3) * HH + m0 + (c1 & 7);
    __syncthreads();

    for (int t = 0; t < TT; t++) {
        const float* __restrict__ hsrc = g_h[t & 1];
        float* __restrict__ hdst = g_h[(t + 1) & 1];

        float xv[2][2][2];
        #pragma unroll
        for (int pi = 0; pi < 2; pi++) {
            int r = pi * 32 + 2 * tx;
            size_t base = ((size_t)t * BB + r0 + r) * GG;
            xv[pi][0][0] = g_xproj[base + gcol0];
            xv[pi][0][1] = g_xproj[base + GG + gcol0];
            xv[pi][1][0] = g_xproj[base + gcol1];
            xv[pi][1][1] = g_xproj[base + GG + gcol1];
        }

        ull acc[2][2];
        acc[0][0] = acc[0][1] = acc[1][0] = acc[1][1] = 0ull;

        float4 rv0 = *(const float4*)&hsrc[(size_t)(r0 + lr) * HH + lk4 * 4];
        float4 rv1 = *(const float4*)&hsrc[(size_t)(r0 + lr2) * HH + lk42 * 4];

        for (int ch = 0; ch < 16; ch++) {
            float* hb = h_sb + (ch & 1) * LP_HS_SZ;
            hb[(lk4 * 4 + 0) * HS_STRIDE + lr] = rv0.x;
            hb[(lk4 * 4 + 1) * HS_STRIDE + lr] = rv0.y;
            hb[(lk4 * 4 + 2) * HS_STRIDE + lr] = rv0.z;
            hb[(lk4 * 4 + 3) * HS_STRIDE + lr] = rv0.w;
            hb[(lk42 * 4 + 0) * HS_STRIDE + lr2] = rv1.x;
            hb[(lk42 * 4 + 1) * HS_STRIDE + lr2] = rv1.y;
            hb[(lk42 * 4 + 2) * HS_STRIDE + lr2] = rv1.z;
            hb[(lk42 * 4 + 3) * HS_STRIDE + lr2] = rv1.w;
            __syncthreads();
            if (ch < 15) {
                int kn = (ch + 1) * 32;
                rv0 = *(const float4*)&hsrc[(size_t)(r0 + lr) * HH + kn + lk4 * 4];
                rv1 = *(const float4*)&hsrc[(size_t)(r0 + lr2) * HH + kn + lk42 * 4];
            }
            int kk0 = ch * 32;
            #pragma unroll
            for (int k = 0; k < 32; k++) {
                ull a0 = *(const ull*)&hb[k * HS_STRIDE + 2 * tx];
                ull a1 = *(const ull*)&hb[k * HS_STRIDE + 32 + 2 * tx];
                ulonglong2 b = *(const ulonglong2*)&Wd[(size_t)(kk0 + k) * 64 + ty * 4];
                fma2(acc[0][0], a0, b.x); fma2(acc[0][1], a0, b.y);
                fma2(acc[1][0], a1, b.x); fma2(acc[1][1], a1, b.y);
            }
        }

        #pragma unroll
        for (int pi = 0; pi < 2; pi++) {
            float2 v0 = unpack2(acc[pi][0]);
            float2 v1 = unpack2(acc[pi][1]);
            int r = pi * 32 + 2 * tx;
            gs[r * 33 + c0]       = v0.x + xv[pi][0][0];
            gs[(r + 1) * 33 + c0] = v0.y + xv[pi][0][1];
            gs[r * 33 + c1]       = v1.x + xv[pi][1][0];
            gs[(r + 1) * 33 + c1] = v1.y + xv[pi][1][1];
        }
        __syncthreads();

        #pragma unroll
        for (int e = 0; e < 2; e++) {
            int p = tid * 2 + e;
            int r = p >> 3, mi = p & 7;
            float gi = gs[r * 33 + mi];
            float gf = gs[r * 33 + 8 + mi];
            float gg = gs[r * 33 + 16 + mi];
            float go = gs[r * 33 + 24 + mi];
            float cn = sigf(gf) * creg[e] + sigf(gi) * tanhf(gg);
            float h = sigf(go) * tanhf(cn);
            creg[e] = cn;
            hdst[(size_t)(r0 + r) * HH + m0 + mi] = h;
            __half hh = __float2half(h);
            __half hl = __float2half(h - __half2float(hh));
            size_t ao = ((size_t)t * BB + r0 + r) * KP + m0 + mi;
            g_Ah[ao] = hh;
            g_Al[ao] = hl;
        }

        __syncthreads();
        if (tid == 0) {
            __threadfence();
            atomicAdd(&g_barrier, 1u);
            unsigned tgt = (unsigned)(t + 1) * LSTM_CTAS;
            while (*(volatile unsigned*)&g_barrier < tgt) { }
            __threadfence();
        }
        __syncthreads();
    }
}

// ================= fp16 convert of W_lin (single copy) =================
__global__ void k_cvtB(const float* __restrict__ W) {
    int idx = blockIdx.x * blockDim.x + threadIdx.x;   // over NP * (KP/4)
    if (idx >= NP * (KP / 4)) return;
    int row = idx / (KP / 4);
    int c4 = (idx % (KP / 4)) * 4;
    float v[4] = {0.f, 0.f, 0.f, 0.f};
    if (row < NITEMS) {
        #pragma unroll
        for (int j = 0; j < 4; j++) {
            int c = c4 + j;
            if (c < KL) v[j] = W[(size_t)row * KL + c];
        }
    }
    size_t o = (size_t)row * KP + c4;
    *(__half2*)&g_B[o]     = __half2(__float2half(v[0]), __float2half(v[1]));
    *(__half2*)&g_B[o + 2] = __half2(__float2half(v[2]), __float2half(v[3]));
}

// ================= final linear: fp16 split-A x single-B, 17 stages =============
// CTA 128x256, 8 warps (2x4), warp tile 64x64. Per stage: load Ah,Al,B tiles once;
// run MMA with Ah then Al against the same staged B (B traffic halved vs 2 passes).
#define LIN_AT_BYTES (128 * LDS_PAD * 2)   // 10240
#define LIN_BT_BYTES (256 * LDS_PAD * 2)   // 20480
#define LIN_SM_BYTES (4 * LIN_AT_BYTES + 2 * LIN_BT_BYTES + 256 * 4)

__global__ __launch_bounds__(256) void k_lin_hmma(const float* __restrict__ b_lin,
                                                  float* __restrict__ out)
{
    extern __shared__ __align__(16) char lsm[];
    const uint32_t ahB0 = smem_u32(lsm);
    const uint32_t alB0 = ahB0 + 2 * LIN_AT_BYTES;
    const uint32_t bB0  = ahB0 + 4 * LIN_AT_BYTES;
    float* bias_s = (float*)(lsm + 4 * LIN_AT_BYTES + 2 * LIN_BT_BYTES);

    const int tid = threadIdx.x;
    const int lane = tid & 31;
    const int wid = tid >> 5;
    const int warp_m = wid & 1;        // 0..1 -> m offset *64
    const int warp_n = wid >> 1;       // 0..3 -> n offset *64
    const int tb0 = blockIdx.x * 128;  // row block (fast dim -> B reuse in L2)
    const int v0  = blockIdx.y * 256;  // item block

    {
        int v = v0 + tid;
        bias_s[tid] = (v < NITEMS) ? b_lin[v] : 0.f;
    }

    float c[4][8][4];
    #pragma unroll
    for (int mi = 0; mi < 4; mi++)
        #pragma unroll
        for (int ni = 0; ni < 8; ni++)
            #pragma unroll
            for (int e = 0; e < 4; e++) c[mi][ni][e] = 0.f;

    auto load_stage = [&](int s, int d) {
        int kk = s * 32;
        const __half* AhS = g_Ah + (size_t)tb0 * KP + kk;
        const __half* AlS = g_Al + (size_t)tb0 * KP + kk;
        const __half* BS  = g_B  + (size_t)v0  * KP + kk;
        uint32_t ahB = ahB0 + d * LIN_AT_BYTES;
        uint32_t alB = alB0 + d * LIN_AT_BYTES;
        uint32_t bB  = bB0  + d * LIN_BT_BYTES;
        #pragma unroll
        for (int it = 0; it < 2; it++) {           // A tiles: 512 chunks each
            int idx = tid + it * 256;
            int r = idx >> 2, c16 = idx & 3;
            CP_ASYNC16(ahB + (r * LDS_PAD + c16 * 8) * 2,
                       (const char*)(AhS + (size_t)r * KP + c16 * 8));
            CP_ASYNC16(alB + (r * LDS_PAD + c16 * 8) * 2,
                       (const char*)(AlS + (size_t)r * KP + c16 * 8));
        }
        #pragma unroll
        for (int it = 0; it < 4; it++) {           // B tile: 1024 chunks
            int idx = tid + it * 256;
            int r = idx >> 2, c16 = idx & 3;
            CP_ASYNC16(bB + (r * LDS_PAD + c16 * 8) * 2,
                       (const char*)(BS + (size_t)r * KP + c16 * 8));
        }
        CP_COMMIT();
    };

    load_stage(0, 0);

    for (int s = 0; s < LIN_STAGES; s++) {
        int d = s & 1;
        if (s + 1 < LIN_STAGES) {
            load_stage(s + 1, (s + 1) & 1);
            CP_WAIT(1);
        } else {
            CP_WAIT(0);
        }
        __syncthreads();

        uint32_t ahB = ahB0 + d * LIN_AT_BYTES;
        uint32_t alB = alB0 + d * LIN_AT_BYTES;
        uint32_t bB  = bB0  + d * LIN_BT_BYTES;
        #pragma unroll
        for (int ks = 0; ks < 2; ks++) {
            uint32_t b[8][2];
            #pragma unroll
            for (int q = 0; q < 4; q++) {
                int row = warp_n * 64 + q * 16 + (lane & 7) + ((lane >> 4) & 1) * 8;
                int col = ks * 16 + ((lane >> 3) & 1) * 8;
                LDSM_X4(b[2 * q][0], b[2 * q][1], b[2 * q + 1][0], b[2 * q + 1][1],
                        bB + (row * LDS_PAD + col) * 2);
            }
            uint32_t a[4][4];
            #pragma unroll
            for (int mi = 0; mi < 4; mi++) {       // pass 1: Ah
                int row = warp_m * 64 + mi * 16 + (lane & 15);
                int col = ks * 16 + (lane >> 4) * 8;
                LDSM_X4(a[mi][0], a[mi][1], a[mi][2], a[mi][3],
                        ahB + (row * LDS_PAD + col) * 2);
            }
            #pragma unroll
            for (int mi = 0; mi < 4; mi++)
                #pragma unroll
                for (int ni = 0; ni < 8; ni++)
                    MMA16816H(c[mi][ni][0], c[mi][ni][1], c[mi][ni][2], c[mi][ni][3],
                              a[mi][0], a[mi][1], a[mi][2], a[mi][3],
                              b[ni][0], b[ni][1]);
            #pragma unroll
            for (int mi = 0; mi < 4; mi++) {       // pass 2: Al (same B regs)
                int row = warp_m * 64 + mi * 16 + (lane & 15);
                int col = ks * 16 + (lane >> 4) * 8;
                LDSM_X4(a[mi][0], a[mi][1], a[mi][2], a[mi][3],
                        alB + (row * LDS_PAD + col) * 2);
            }
            #pragma unroll
            for (int mi = 0; mi < 4; mi++)
                #pragma unroll
                for (int ni = 0; ni < 8; ni++)
                    MMA16816H(c[mi][ni][0], c[mi][ni][1], c[mi][ni][2], c[mi][ni][3],
                              a[mi][0], a[mi][1], a[mi][2], a[mi][3],
                              b[ni][0], b[ni][1]);
        }
        __syncthreads();
    }

    // epilogue: direct float2 stores with bias
    #pragma unroll
    for (int mi = 0; mi < 4; mi++) {
        int m = tb0 + warp_m * 64 + mi * 16 + (lane >> 2);
        #pragma unroll
        for (int ni = 0; ni < 8; ni++) {
            int nl = warp_n * 64 + ni * 8 + (lane & 3) * 2;
            int n = v0 + nl;
            if (n < NITEMS) {
                float b0v = bias_s[nl], b1v = bias_s[nl + 1];
                *(float2*)&out[(size_t)m * NITEMS + n] =
                    make_float2(c[mi][ni][0] + b0v, c[mi][ni][1] + b1v);
                *(float2*)&out[(size_t)(m + 8) * NITEMS + n] =
                    make_float2(c[mi][ni][2] + b0v, c[mi][ni][3] + b1v);
            }
        }
    }
}

// ================= l2 norm =================
__global__ void k_l2zero() { if (threadIdx.x < 2) g_l2[threadIdx.x] = 0.f; }

__global__ void k_l2reduce(const float* __restrict__ W_lin, const float* __restrict__ b_lin) {
    __shared__ float sh[256];
    int tid = threadIdx.x;
    int stride = gridDim.x * blockDim.x;
    float sw = 0.f;
    for (size_t i = blockIdx.x * blockDim.x + tid; i < (size_t)NITEMS * KL; i += stride) {
        float v = W_lin[i]; sw += v * v;
    }
    float sb = 0.f;
    for (int i = blockIdx.x * blockDim.x + tid; i < NITEMS; i += stride) {
        float v = b_lin[i]; sb += v * v;
    }
    sh[tid] = sw; __syncthreads();
    for (int s = 128; s > 0; s >>= 1) { if (tid < s) sh[tid] += sh[tid + s]; __syncthreads(); }
    if (tid == 0) atomicAdd(&g_l2[0], sh[0]);
    __syncthreads();
    sh[tid] = sb; __syncthreads();
    for (int s = 128; s > 0; s >>= 1) { if (tid < s) sh[tid] += sh[tid + s]; __syncthreads(); }
    if (tid == 0) atomicAdd(&g_l2[1], sh[0]);
}

__global__ void k_l2final(float* __restrict__ out, int has_scalar) {
    if (has_scalar && threadIdx.x == 0)
        out[NPN] = sqrtf(g_l2[0]) + sqrtf(g_l2[1]);
}

// ================= launch =================
extern "C" void kernel_launch(void* const* d_in, const int* in_sizes, int n_in,
                              void* d_out, int out_size) {
    const int*   act   = (const int*)  d_in[0];
    const float* rew   = (const float*)d_in[1];
    const float* stat  = (const float*)d_in[2];
    const float* hx    = (const float*)d_in[3];
    const float* cx    = (const float*)d_in[4];
    const float* emb   = (const float*)d_in[5];
    const float* W_ih  = (const float*)d_in[6];
    const float* W_hh  = (const float*)d_in[7];
    const float* b_ih  = (const float*)d_in[8];
    const float* b_hh  = (const float*)d_in[9];
    const float* W_lin = (const float*)d_in[10];
    const float* b_lin = (const float*)d_in[11];
    float* out = (float*)d_out;

    const int lstm_smem = LP_SM_FLOATS * (int)sizeof(float);
    cudaFuncSetAttribute(k_lstm_persist,
                         cudaFuncAttributeMaxDynamicSharedMemorySize, lstm_smem);
    cudaFuncSetAttribute(k_lin_hmma,
                         cudaFuncAttributeMaxDynamicSharedMemorySize, LIN_SM_BYTES);

    k_init<<<(BB * HH + 255) / 256, 256>>>(hx);
    k_ars<<<(TT * BB * 32 + 255) / 256, 256>>>(act, rew, stat, emb);
    k_statsplit<<<(TT * BB * 32 + 255) / 256, 256>>>(stat);
    k_xproj<<<dim3(GG / 128, TT * BB / 128), 256>>>(W_ih, b_ih, b_hh);
    k_cvtB<<<(NP * (KP / 4) + 255) / 256, 256>>>(W_lin);

    // all 100 LSTM steps in one persistent launch (128 CTAs, grid barrier)
    k_lstm_persist<<<dim3(64, 2), 256, lstm_smem>>>(W_hh, cx);

    // grid.x = row blocks (fast) so consecutive CTAs share the same B column block
    k_lin_hmma<<<dim3(TT * BB / 128, NP / 256), 256, LIN_SM_BYTES>>>(b_lin, out);

    k_l2zero<<<1, 32>>>();
    k_l2reduce<<<512, 256>>>(W_lin, b_lin);
    k_l2final<<<1, 32>>>(out, out_size > NPN ? 1 : 0);
}

// round 15
// speedup vs baseline: 1.5164x; 1.5164x over previous
#include <cuda_runtime.h>
#include <cuda_fp16.h>
#include <math.h>
#include <stdint.h>

#define TT 100
#define BB 128
#define HH 512
#define GG 2048            // 4*H
#define NIN 128            // rnn input dim
#define NITEMS 10000
#define KL 544             // H + SDIM
#define NPN 128000000      // TT*BB*NITEMS
#define KP 576             // K padded (row stride for split buffers)
#define NP 10240           // items padded to 40*256

// HMMA GEMM config for final linear (fp16 split-A, single-B, 17 K-stages x 2 A-passes)
#define LIN_STAGES 17      // 544/32
#define LDS_PAD 40         // 32 data + 8 pad halves per smem row

// persistent LSTM config
#define LSTM_CTAS 128
#define HS_STRIDE 66       // h_s k-row stride: EVEN (f32x2 pair alignment)

typedef unsigned long long ull;

// ---------------- static device scratch (no runtime allocation) ----------------
__device__ float g_ars[TT * BB * NIN];
__device__ float g_xproj[TT * BB * GG];
__device__ float g_h[2][BB * HH];
__device__ float g_l2[2];
__device__ unsigned g_barrier;
__device__ __half g_Ah[(size_t)TT * BB * KP];   // fp16 hi(A)
__device__ __half g_Al[(size_t)TT * BB * KP];   // fp16 lo(A)
__device__ __half g_B[(size_t)NP * KP];         // fp16 W_lin (single copy)

// ---------------- f32x2 helpers ----------------
__device__ __forceinline__ ull pack2(float x, float y) {
    ull v; asm("mov.b64 %0,{%1,%2};" : "=l"(v) : "f"(x), "f"(y)); return v;
}
__device__ __forceinline__ float2 unpack2(ull v) {
    float2 f; asm("mov.b64 {%0,%1},%2;" : "=f"(f.x), "=f"(f.y) : "l"(v)); return f;
}
__device__ __forceinline__ void fma2(ull &c, ull a, ull b) {
    asm("fma.rn.f32x2 %0,%1,%2,%3;" : "=l"(c) : "l"(a), "l"(b), "l"(c));
}
__device__ __forceinline__ float sigf(float x) { return 1.0f / (1.0f + expf(-x)); }

__device__ __forceinline__ uint32_t smem_u32(const void* p) {
    uint32_t a;
    asm("{ .reg .u64 t; cvta.to.shared.u64 t, %1; cvt.u32.u64 %0, t; }" : "=r"(a) : "l"(p));
    return a;
}

// ---------------- cp.async / ldmatrix / mma (baseline sm_80 PTX) ----------------
#define CP_ASYNC16(sdst, gsrc) \
    asm volatile("cp.async.cg.shared.global [%0], [%1], 16;" :: "r"(sdst), "l"(gsrc))
#define CP_COMMIT() asm volatile("cp.async.commit_group;" ::: "memory")
#define CP_WAIT(n)  asm volatile("cp.async.wait_group %0;" :: "n"(n) : "memory")

#define LDSM_X4(r0, r1, r2, r3, addr) \
    asm volatile("ldmatrix.sync.aligned.m8n8.x4.shared.b16 {%0,%1,%2,%3}, [%4];" \
        : "=r"(r0), "=r"(r1), "=r"(r2), "=r"(r3) : "r"(addr))

#define MMA16816H(c0, c1, c2, c3, a0, a1, a2, a3, b0, b1) \
    asm volatile("mma.sync.aligned.m16n8k16.row.col.f32.f16.f16.f32 " \
        "{%0,%1,%2,%3}, {%4,%5,%6,%7}, {%8,%9}, {%0,%1,%2,%3};" \
        : "+f"(c0), "+f"(c1), "+f"(c2), "+f"(c3) \
        : "r"(a0), "r"(a1), "r"(a2), "r"(a3), "r"(b0), "r"(b1))

// ================= init (also resets grid barrier each replay) =================
__global__ void k_init(const float* __restrict__ hx) {
    int i = blockIdx.x * blockDim.x + threadIdx.x;
    if (i < BB * HH) g_h[0][i] = hx[i];
    if (i == 0) g_barrier = 0u;
}

// ================= build ars =================
__global__ void k_ars(const int* __restrict__ act, const float* __restrict__ rew,
                      const float* __restrict__ stat, const float* __restrict__ emb) {
    int idx = blockIdx.x * blockDim.x + threadIdx.x;
    if (idx >= TT * BB * 32) return;
    int tb = idx >> 5;
    int k = (idx & 31) * 4;
    float4 v;
    if (k < 64) {
        v = *(const float4*)&emb[(size_t)act[tb] * 64 + k];
    } else if (k < 96) {
        float r = rew[tb];
        int ri = (int)floorf((32.0f * (2.0f - r)) / 4.0f);
        int kb = k - 64;
        v.x = (ri == kb    ) ? 1.f : 0.f;
        v.y = (ri == kb + 1) ? 1.f : 0.f;
        v.z = (ri == kb + 2) ? 1.f : 0.f;
        v.w = (ri == kb + 3) ? 1.f : 0.f;
    } else {
        v = *(const float4*)&stat[(size_t)tb * 32 + (k - 96)];
    }
    *(float4*)&g_ars[(size_t)tb * NIN + k] = v;
}

// ================= statsplit: A cols 512..543 = fp16 split(stat) =================
__global__ void k_statsplit(const float* __restrict__ stat) {
    int idx = blockIdx.x * blockDim.x + threadIdx.x;   // over 12800*32
    if (idx >= TT * BB * 32) return;
    int tb = idx >> 5, s = idx & 31;
    float v = stat[(size_t)tb * 32 + s];
    __half hh = __float2half(v);
    __half hl = __float2half(v - __half2float(hh));
    size_t o = (size_t)tb * KP + HH + s;
    g_Ah[o] = hh;
    g_Al[o] = hl;
}

// ================= x_proj (unchanged, known passing; clock diagnostic) ==========
__global__ __launch_bounds__(256, 2) void k_xproj(
    const float* __restrict__ W_ih, const float* __restrict__ b_ih,
    const float* __restrict__ b_hh)
{
    __shared__ __align__(16) float A_s[8][132];
    __shared__ __align__(16) float B2_s[8][264];
    const int tid = threadIdx.x;
    const int g0  = blockIdx.x * 128;
    const int tb0 = blockIdx.y * 128;
    const int tx = tid & 15;
    const int ty = tid >> 4;
    const int mf = tid >> 1;
    const int kf = (tid & 1) * 4;

    ull acc[4][8];
    #pragma unroll
    for (int i = 0; i < 4; i++)
        #pragma unroll
        for (int j = 0; j < 8; j++) acc[i][j] = 0ull;

    float4 rA = *(const float4*)&g_ars[(size_t)(tb0 + mf) * NIN + kf];
    float4 rB = *(const float4*)&W_ih[(size_t)(g0 + mf) * NIN + kf];

    for (int kt = 0; kt < NIN / 8; kt++) {
        A_s[kf + 0][mf] = rA.x; A_s[kf + 1][mf] = rA.y;
        A_s[kf + 2][mf] = rA.z; A_s[kf + 3][mf] = rA.w;
        *(ull*)&B2_s[kf + 0][2 * mf] = pack2(rB.x, rB.x);
        *(ull*)&B2_s[kf + 1][2 * mf] = pack2(rB.y, rB.y);
        *(ull*)&B2_s[kf + 2][2 * mf] = pack2(rB.z, rB.z);
        *(ull*)&B2_s[kf + 3][2 * mf] = pack2(rB.w, rB.w);
        __syncthreads();
        if (kt + 1 < NIN / 8) {
            int k0n = (kt + 1) * 8;
            rA = *(const float4*)&g_ars[(size_t)(tb0 + mf) * NIN + k0n + kf];
            rB = *(const float4*)&W_ih[(size_t)(g0 + mf) * NIN + k0n + kf];
        }
        #pragma unroll
        for (int k = 0; k < 8; k++) {
            ulonglong2 a01 = *(const ulonglong2*)&A_s[k][tx * 8];
            ulonglong2 a23 = *(const ulonglong2*)&A_s[k][tx * 8 + 4];
            ull a[4] = {a01.x, a01.y, a23.x, a23.y};
            #pragma unroll
            for (int jh = 0; jh < 2; jh++) {
                ulonglong2 b01 = *(const ulonglong2*)&B2_s[k][ty * 16 + jh * 8];
                ulonglong2 b23 = *(const ulonglong2*)&B2_s[k][ty * 16 + jh * 8 + 4];
                ull b[4] = {b01.x, b01.y, b23.x, b23.y};
                #pragma unroll
                for (int i = 0; i < 4; i++)
                    #pragma unroll
                    for (int j = 0; j < 4; j++)
                        fma2(acc[i][jh * 4 + j], a[i], b[j]);
            }
        }
        __syncthreads();
    }
    float bs[8];
    #pragma unroll
    for (int j = 0; j < 8; j++) {
        int g = g0 + ty * 8 + j;
        bs[j] = b_ih[g] + b_hh[g];
    }
    #pragma unroll
    for (int rp = 0; rp < 4; rp++) {
        float lo[8], hi[8];
        #pragma unroll
        for (int j = 0; j < 8; j++) {
            float2 c = unpack2(acc[rp][j]);
            lo[j] = c.x + bs[j]; hi[j] = c.y + bs[j];
        }
        int row = tb0 + tx * 8 + rp * 2;
        size_t o0 = (size_t)row * GG + g0 + ty * 8;
        *(float4*)&g_xproj[o0]          = make_float4(lo[0], lo[1], lo[2], lo[3]);
        *(float4*)&g_xproj[o0 + 4]      = make_float4(lo[4], lo[5], lo[6], lo[7]);
        *(float4*)&g_xproj[o0 + GG]     = make_float4(hi[0], hi[1], hi[2], hi[3]);
        *(float4*)&g_xproj[o0 + GG + 4] = make_float4(hi[4], hi[5], hi[6], hi[7]);
    }
}

// ================= persistent LSTM (unchanged from R13/R14) =====================
#define LP_WD_SZ   (512 * 64)
#define LP_HS_OFF  LP_WD_SZ
#define LP_HS_SZ   (32 * HS_STRIDE)
#define LP_GS_OFF  (LP_HS_OFF + 2 * LP_HS_SZ + 2)
#define LP_SM_FLOATS (LP_GS_OFF + 64 * 33 + 4)

__global__ __launch_bounds__(256) void k_lstm_persist(
    const float* __restrict__ W_hh, const float* __restrict__ cx)
{
    extern __shared__ __align__(16) float smf[];
    float* Wd   = smf;
    float* h_sb = smf + LP_HS_OFF;
    float* gs   = smf + LP_GS_OFF;

    const int tid = threadIdx.x;
    const int m0 = blockIdx.x * 8;
    const int r0 = blockIdx.y * 64;
    const int tx = tid & 15;
    const int ty = tid >> 4;
    const int lr  = tid >> 3,  lk4  = tid & 7;
    const int lr2 = (tid + 256) >> 3, lk42 = tid & 7;

    #pragma unroll
    for (int it = 0; it < 16; it++) {
        int idx = tid + it * 256;
        int c = idx >> 7;
        int k4 = idx & 127;
        int grow = (c >> 3) * HH + m0 + (c & 7);
        float4 v = *(const float4*)&W_hh[(size_t)grow * HH + k4 * 4];
        *(ull*)&Wd[(size_t)(k4 * 4 + 0) * 64 + 2 * c] = pack2(v.x, v.x);
        *(ull*)&Wd[(size_t)(k4 * 4 + 1) * 64 + 2 * c] = pack2(v.y, v.y);
        *(ull*)&Wd[(size_t)(k4 * 4 + 2) * 64 + 2 * c] = pack2(v.z, v.z);
        *(ull*)&Wd[(size_t)(k4 * 4 + 3) * 64 + 2 * c] = pack2(v.w, v.w);
    }

    float creg[2];
    #pragma unroll
    for (int e = 0; e < 2; e++) {
        int p = tid * 2 + e;
        creg[e] = cx[(size_t)(r0 + (p >> 3)) * HH + m0 + (p & 7)];
    }

    const int c0 = 2 * ty, c1 = 2 * ty + 1;
    const int gcol0 = (c0 >> 3) * HH + m0 + (c0 & 7);
    const int gcol1 = (c1 >> 3) * HH + m0 + (c1 & 7);
    __syncthreads();

    for (int t = 0; t < TT; t++) {
        const float* __restrict__ hsrc = g_h[t & 1];
        float* __restrict__ hdst = g_h[(t + 1) & 1];

        float xv[2][2][2];
        #pragma unroll
        for (int pi = 0; pi < 2; pi++) {
            int r = pi * 32 + 2 * tx;
            size_t base = ((size_t)t * BB + r0 + r) * GG;
            xv[pi][0][0] = g_xproj[base + gcol0];
            xv[pi][0][1] = g_xproj[base + GG + gcol0];
            xv[pi][1][0] = g_xproj[base + gcol1];
            xv[pi][1][1] = g_xproj[base + GG + gcol1];
        }

        ull acc[2][2];
        acc[0][0] = acc[0][1] = acc[1][0] = acc[1][1] = 0ull;

        float4 rv0 = *(const float4*)&hsrc[(size_t)(r0 + lr) * HH + lk4 * 4];
        float4 rv1 = *(const float4*)&hsrc[(size_t)(r0 + lr2) * HH + lk42 * 4];

        for (int ch = 0; ch < 16; ch++) {
            float* hb = h_sb + (ch & 1) * LP_HS_SZ;
            hb[(lk4 * 4 + 0) * HS_STRIDE + lr] = rv0.x;
            hb[(lk4 * 4 + 1) * HS_STRIDE + lr] = rv0.y;
            hb[(lk4 * 4 + 2) * HS_STRIDE + lr] = rv0.z;
            hb[(lk4 * 4 + 3) * HS_STRIDE + lr] = rv0.w;
            hb[(lk42 * 4 + 0) * HS_STRIDE + lr2] = rv1.x;
            hb[(lk42 * 4 + 1) * HS_STRIDE + lr2] = rv1.y;
            hb[(lk42 * 4 + 2) * HS_STRIDE + lr2] = rv1.z;
            hb[(lk42 * 4 + 3) * HS_STRIDE + lr2] = rv1.w;
            __syncthreads();
            if (ch < 15) {
                int kn = (ch + 1) * 32;
                rv0 = *(const float4*)&hsrc[(size_t)(r0 + lr) * HH + kn + lk4 * 4];
                rv1 = *(const float4*)&hsrc[(size_t)(r0 + lr2) * HH + kn + lk42 * 4];
            }
            int kk0 = ch * 32;
            #pragma unroll
            for (int k = 0; k < 32; k++) {
                ull a0 = *(const ull*)&hb[k * HS_STRIDE + 2 * tx];
                ull a1 = *(const ull*)&hb[k * HS_STRIDE + 32 + 2 * tx];
                ulonglong2 b = *(const ulonglong2*)&Wd[(size_t)(kk0 + k) * 64 + ty * 4];
                fma2(acc[0][0], a0, b.x); fma2(acc[0][1], a0, b.y);
                fma2(acc[1][0], a1, b.x); fma2(acc[1][1], a1, b.y);
            }
        }

        #pragma unroll
        for (int pi = 0; pi < 2; pi++) {
            float2 v0 = unpack2(acc[pi][0]);
            float2 v1 = unpack2(acc[pi][1]);
            int r = pi * 32 + 2 * tx;
            gs[r * 33 + c0]       = v0.x + xv[pi][0][0];
            gs[(r + 1) * 33 + c0] = v0.y + xv[pi][0][1];
            gs[r * 33 + c1]       = v1.x + xv[pi][1][0];
            gs[(r + 1) * 33 + c1] = v1.y + xv[pi][1][1];
        }
        __syncthreads();

        #pragma unroll
        for (int e = 0; e < 2; e++) {
            int p = tid * 2 + e;
            int r = p >> 3, mi = p & 7;
            float gi = gs[r * 33 + mi];
            float gf = gs[r * 33 + 8 + mi];
            float gg = gs[r * 33 + 16 + mi];
            float go = gs[r * 33 + 24 + mi];
            float cn = sigf(gf) * creg[e] + sigf(gi) * tanhf(gg);
            float h = sigf(go) * tanhf(cn);
            creg[e] = cn;
            hdst[(size_t)(r0 + r) * HH + m0 + mi] = h;
            __half hh = __float2half(h);
            __half hl = __float2half(h - __half2float(hh));
            size_t ao = ((size_t)t * BB + r0 + r) * KP + m0 + mi;
            g_Ah[ao] = hh;
            g_Al[ao] = hl;
        }

        __syncthreads();
        if (tid == 0) {
            __threadfence();
            atomicAdd(&g_barrier, 1u);
            unsigned tgt = (unsigned)(t + 1) * LSTM_CTAS;
            while (*(volatile unsigned*)&g_barrier < tgt) { }
            __threadfence();
        }
        __syncthreads();
    }
}

// ================= fp16 convert of W_lin (single copy) =================
__global__ void k_cvtB(const float* __restrict__ W) {
    int idx = blockIdx.x * blockDim.x + threadIdx.x;   // over NP * (KP/4)
    if (idx >= NP * (KP / 4)) return;
    int row = idx / (KP / 4);
    int c4 = (idx % (KP / 4)) * 4;
    float v[4] = {0.f, 0.f, 0.f, 0.f};
    if (row < NITEMS) {
        #pragma unroll
        for (int j = 0; j < 4; j++) {
            int c = c4 + j;
            if (c < KL) v[j] = W[(size_t)row * KL + c];
        }
    }
    size_t o = (size_t)row * KP + c4;
    *(__half2*)&g_B[o]     = __half2(__float2half(v[0]), __float2half(v[1]));
    *(__half2*)&g_B[o + 2] = __half2(__float2half(v[2]), __float2half(v[3]));
}

// ================= final linear: fp16 split-A x single-B, triple-buffered ======
// CTA 128x256, 8 warps (2x4), warp tile 64x64. Per K-stage: stage Ah,Al,B once,
// run MMA with Ah then Al against the same staged B. 3 SMEM buffers keep 2
// cp.async groups in flight -> each stage's L2 latency hidden by a full stage
// of MMA work.
#define LIN_AT_BYTES (128 * LDS_PAD * 2)   // 10240 per A tile
#define LIN_BT_BYTES (256 * LDS_PAD * 2)   // 20480
#define LIN_STAGE_BYTES (2 * LIN_AT_BYTES + LIN_BT_BYTES)   // 40960
#define LIN_SM_BYTES (3 * LIN_STAGE_BYTES + 256 * 4)

__global__ __launch_bounds__(256) void k_lin_hmma(const float* __restrict__ b_lin,
                                                  float* __restrict__ out)
{
    extern __shared__ __align__(16) char lsm[];
    const uint32_t sb0 = smem_u32(lsm);
    float* bias_s = (float*)(lsm + 3 * LIN_STAGE_BYTES);

    const int tid = threadIdx.x;
    const int lane = tid & 31;
    const int wid = tid >> 5;
    const int warp_m = wid & 1;        // 0..1 -> m offset *64
    const int warp_n = wid >> 1;       // 0..3 -> n offset *64
    const int tb0 = blockIdx.x * 128;  // row block (fast dim -> B reuse in L2)
    const int v0  = blockIdx.y * 256;  // item block

    {
        int v = v0 + tid;
        bias_s[tid] = (v < NITEMS) ? b_lin[v] : 0.f;
    }

    float c[4][8][4];
    #pragma unroll
    for (int mi = 0; mi < 4; mi++)
        #pragma unroll
        for (int ni = 0; ni < 8; ni++)
            #pragma unroll
            for (int e = 0; e < 4; e++) c[mi][ni][e] = 0.f;

    auto load_stage = [&](int s, int d) {
        int kk = s * 32;
        const __half* AhS = g_Ah + (size_t)tb0 * KP + kk;
        const __half* AlS = g_Al + (size_t)tb0 * KP + kk;
        const __half* BS  = g_B  + (size_t)v0  * KP + kk;
        uint32_t ahB = sb0 + d * LIN_STAGE_BYTES;
        uint32_t alB = ahB + LIN_AT_BYTES;
        uint32_t bB  = ahB + 2 * LIN_AT_BYTES;
        #pragma unroll
        for (int it = 0; it < 2; it++) {           // A tiles: 512 chunks each
            int idx = tid + it * 256;
            int r = idx >> 2, c16 = idx & 3;
            CP_ASYNC16(ahB + (r * LDS_PAD + c16 * 8) * 2,
                       (const char*)(AhS + (size_t)r * KP + c16 * 8));
            CP_ASYNC16(alB + (r * LDS_PAD + c16 * 8) * 2,
                       (const char*)(AlS + (size_t)r * KP + c16 * 8));
        }
        #pragma unroll
        for (int it = 0; it < 4; it++) {           // B tile: 1024 chunks
            int idx = tid + it * 256;
            int r = idx >> 2, c16 = idx & 3;
            CP_ASYNC16(bB + (r * LDS_PAD + c16 * 8) * 2,
                       (const char*)(BS + (size_t)r * KP + c16 * 8));
        }
        CP_COMMIT();
    };

    load_stage(0, 0);
    load_stage(1, 1);

    for (int s = 0; s < LIN_STAGES; s++) {
        CP_WAIT(1);            // group for stage s complete (s+1 may be pending)
        __syncthreads();       // make staged data visible to all warps
        if (s + 2 < LIN_STAGES) load_stage(s + 2, (s + 2) % 3);

        uint32_t ahB = sb0 + (s % 3) * LIN_STAGE_BYTES;
        uint32_t alB = ahB + LIN_AT_BYTES;
        uint32_t bB  = ahB + 2 * LIN_AT_BYTES;
        #pragma unroll
        for (int ks = 0; ks < 2; ks++) {
            uint32_t b[8][2];
            #pragma unroll
            for (int q = 0; q < 4; q++) {
                int row = warp_n * 64 + q * 16 + (lane & 7) + ((lane >> 4) & 1) * 8;
                int col = ks * 16 + ((lane >> 3) & 1) * 8;
                LDSM_X4(b[2 * q][0], b[2 * q][1], b[2 * q + 1][0], b[2 * q + 1][1],
                        bB + (row * LDS_PAD + col) * 2);
            }
            uint32_t a[4][4];
            #pragma unroll
            for (int mi = 0; mi < 4; mi++) {       // pass 1: Ah
                int row = warp_m * 64 + mi * 16 + (lane & 15);
                int col = ks * 16 + (lane >> 4) * 8;
                LDSM_X4(a[mi][0], a[mi][1], a[mi][2], a[mi][3],
                        ahB + (row * LDS_PAD + col) * 2);
            }
            #pragma unroll
            for (int mi = 0; mi < 4; mi++)
                #pragma unroll
                for (int ni = 0; ni < 8; ni++)
                    MMA16816H(c[mi][ni][0], c[mi][ni][1], c[mi][ni][2], c[mi][ni][3],
                              a[mi][0], a[mi][1], a[mi][2], a[mi][3],
                              b[ni][0], b[ni][1]);
            #pragma unroll
            for (int mi = 0; mi < 4; mi++) {       // pass 2: Al (same B regs)
                int row = warp_m * 64 + mi * 16 + (lane & 15);
                int col = ks * 16 + (lane >> 4) * 8;
                LDSM_X4(a[mi][0], a[mi][1], a[mi][2], a[mi][3],
                        alB + (row * LDS_PAD + col) * 2);
            }
            #pragma unroll
            for (int mi = 0; mi < 4; mi++)
                #pragma unroll
                for (int ni = 0; ni < 8; ni++)
                    MMA16816H(c[mi][ni][0], c[mi][ni][1], c[mi][ni][2], c[mi][ni][3],
                              a[mi][0], a[mi][1], a[mi][2], a[mi][3],
                              b[ni][0], b[ni][1]);
        }
        __syncthreads();       // compute done before this buffer is overwritten
    }

    // epilogue: direct float2 stores with bias
    #pragma unroll
    for (int mi = 0; mi < 4; mi++) {
        int m = tb0 + warp_m * 64 + mi * 16 + (lane >> 2);
        #pragma unroll
        for (int ni = 0; ni < 8; ni++) {
            int nl = warp_n * 64 + ni * 8 + (lane & 3) * 2;
            int n = v0 + nl;
            if (n < NITEMS) {
                float b0v = bias_s[nl], b1v = bias_s[nl + 1];
                *(float2*)&out[(size_t)m * NITEMS + n] =
                    make_float2(c[mi][ni][0] + b0v, c[mi][ni][1] + b1v);
                *(float2*)&out[(size_t)(m + 8) * NITEMS + n] =
                    make_float2(c[mi][ni][2] + b0v, c[mi][ni][3] + b1v);
            }
        }
    }
}

// ================= l2 norm =================
__global__ void k_l2zero() { if (threadIdx.x < 2) g_l2[threadIdx.x] = 0.f; }

__global__ void k_l2reduce(const float* __restrict__ W_lin, const float* __restrict__ b_lin) {
    __shared__ float sh[256];
    int tid = threadIdx.x;
    int stride = gridDim.x * blockDim.x;
    float sw = 0.f;
    for (size_t i = blockIdx.x * blockDim.x + tid; i < (size_t)NITEMS * KL; i += stride) {
        float v = W_lin[i]; sw += v * v;
    }
    float sb = 0.f;
    for (int i = blockIdx.x * blockDim.x + tid; i < NITEMS; i += stride) {
        float v = b_lin[i]; sb += v * v;
    }
    sh[tid] = sw; __syncthreads();
    for (int s = 128; s > 0; s >>= 1) { if (tid < s) sh[tid] += sh[tid + s]; __syncthreads(); }
    if (tid == 0) atomicAdd(&g_l2[0], sh[0]);
    __syncthreads();
    sh[tid] = sb; __syncthreads();
    for (int s = 128; s > 0; s >>= 1) { if (tid < s) sh[tid] += sh[tid + s]; __syncthreads(); }
    if (tid == 0) atomicAdd(&g_l2[1], sh[0]);
}

__global__ void k_l2final(float* __restrict__ out, int has_scalar) {
    if (has_scalar && threadIdx.x == 0)
        out[NPN] = sqrtf(g_l2[0]) + sqrtf(g_l2[1]);
}

// ================= launch =================
extern "C" void kernel_launch(void* const* d_in, const int* in_sizes, int n_in,
                              void* d_out, int out_size) {
    const int*   act   = (const int*)  d_in[0];
    const float* rew   = (const float*)d_in[1];
    const float* stat  = (const float*)d_in[2];
    const float* hx    = (const float*)d_in[3];
    const float* cx    = (const float*)d_in[4];
    const float* emb   = (const float*)d_in[5];
    const float* W_ih  = (const float*)d_in[6];
    const float* W_hh  = (const float*)d_in[7];
    const float* b_ih  = (const float*)d_in[8];
    const float* b_hh  = (const float*)d_in[9];
    const float* W_lin = (const float*)d_in[10];
    const float* b_lin = (const float*)d_in[11];
    float* out = (float*)d_out;

    const int lstm_smem = LP_SM_FLOATS * (int)sizeof(float);
    cudaFuncSetAttribute(k_lstm_persist,
                         cudaFuncAttributeMaxDynamicSharedMemorySize, lstm_smem);
    cudaFuncSetAttribute(k_lin_hmma,
                         cudaFuncAttributeMaxDynamicSharedMemorySize, LIN_SM_BYTES);

    k_init<<<(BB * HH + 255) / 256, 256>>>(hx);
    k_ars<<<(TT * BB * 32 + 255) / 256, 256>>>(act, rew, stat, emb);
    k_statsplit<<<(TT * BB * 32 + 255) / 256, 256>>>(stat);
    k_xproj<<<dim3(GG / 128, TT * BB / 128), 256>>>(W_ih, b_ih, b_hh);
    k_cvtB<<<(NP * (KP / 4) + 255) / 256, 256>>>(W_lin);

    // all 100 LSTM steps in one persistent launch (128 CTAs, grid barrier)
    k_lstm_persist<<<dim3(64, 2), 256, lstm_smem>>>(W_hh, cx);

    // grid.x = row blocks (fast) so consecutive CTAs share the same B column block
    k_lin_hmma<<<dim3(TT * BB / 128, NP / 256), 256, LIN_SM_BYTES>>>(b_lin, out);

    k_l2zero<<<1, 32>>>();
    k_l2reduce<<<512, 256>>>(W_lin, b_lin);
    k_l2final<<<1, 32>>>(out, out_size > NPN ? 1 : 0);
}

// round 16
// speedup vs baseline: 2.3706x; 1.5634x over previous
#include <cuda_runtime.h>
#include <cuda_fp16.h>
#include <math.h>
#include <stdint.h>

#define TT 100
#define BB 128
#define HH 512
#define GG 2048            // 4*H
#define NIN 128            // rnn input dim
#define NITEMS 10000
#define KL 544             // H + SDIM
#define NPN 128000000      // TT*BB*NITEMS
#define KP 576             // K padded (row stride for split buffers)
#define NP 10240           // items padded to 40*256

// HMMA GEMM config for final linear (fp16 split-A, single-B, 17 K-stages x 2 A-passes)
#define LIN_STAGES 17      // 544/32
#define LDS_PAD 40         // 32 data + 8 pad halves per smem row

// persistent LSTM config (HMMA)
#define LSTM_CTAS 128
#define WS 520             // smem row stride in halves (1040B: 16B-aligned, bank stride 4)
#define WH_OFF 0           // W_hh hi  [32][WS] halves
#define WL_OFF 16640       // W_hh lo
#define HHS_OFF 33280      // h hi [64][WS]
#define HLS_OFF 66560      // h lo
#define GS_BYTE_OFF 199680 // gates staging float[64][33]
#define LSTM_SM_BYTES 208128

typedef unsigned long long ull;

// ---------------- static device scratch (no runtime allocation) ----------------
__device__ float g_ars[TT * BB * NIN];
__device__ float g_xproj[TT * BB * GG];
__device__ float g_l2[2];
__device__ unsigned g_barrier;
__device__ __half g_Ah[(size_t)TT * BB * KP];   // fp16 hi(h | stat) per t
__device__ __half g_Al[(size_t)TT * BB * KP];   // fp16 lo
__device__ __half g_B[(size_t)NP * KP];         // fp16 W_lin (single copy)
__device__ __half g_h0h[BB * HH];               // split(hx) hi
__device__ __half g_h0l[BB * HH];               // split(hx) lo

// ---------------- f32x2 helpers (used by k_xproj) ----------------
__device__ __forceinline__ ull pack2(float x, float y) {
    ull v; asm("mov.b64 %0,{%1,%2};" : "=l"(v) : "f"(x), "f"(y)); return v;
}
__device__ __forceinline__ float2 unpack2(ull v) {
    float2 f; asm("mov.b64 {%0,%1},%2;" : "=f"(f.x), "=f"(f.y) : "l"(v)); return f;
}
__device__ __forceinline__ void fma2(ull &c, ull a, ull b) {
    asm("fma.rn.f32x2 %0,%1,%2,%3;" : "=l"(c) : "l"(a), "l"(b), "l"(c));
}
__device__ __forceinline__ float sigf(float x) { return 1.0f / (1.0f + expf(-x)); }

__device__ __forceinline__ uint32_t smem_u32(const void* p) {
    uint32_t a;
    asm("{ .reg .u64 t; cvta.to.shared.u64 t, %1; cvt.u32.u64 %0, t; }" : "=r"(a) : "l"(p));
    return a;
}

// ---------------- cp.async / ldmatrix / mma (baseline sm_80 PTX) ----------------
#define CP_ASYNC16(sdst, gsrc) \
    asm volatile("cp.async.cg.shared.global [%0], [%1], 16;" :: "r"(sdst), "l"(gsrc))
#define CP_COMMIT() asm volatile("cp.async.commit_group;" ::: "memory")
#define CP_WAIT(n)  asm volatile("cp.async.wait_group %0;" :: "n"(n) : "memory")

#define LDSM_X4(r0, r1, r2, r3, addr) \
    asm volatile("ldmatrix.sync.aligned.m8n8.x4.shared.b16 {%0,%1,%2,%3}, [%4];" \
        : "=r"(r0), "=r"(r1), "=r"(r2), "=r"(r3) : "r"(addr))
#define LDSM_X2(r0, r1, addr) \
    asm volatile("ldmatrix.sync.aligned.m8n8.x2.shared.b16 {%0,%1}, [%2];" \
        : "=r"(r0), "=r"(r1) : "r"(addr))

#define MMA16816H(c0, c1, c2, c3, a0, a1, a2, a3, b0, b1) \
    asm volatile("mma.sync.aligned.m16n8k16.row.col.f32.f16.f16.f32 " \
        "{%0,%1,%2,%3}, {%4,%5,%6,%7}, {%8,%9}, {%0,%1,%2,%3};" \
        : "+f"(c0), "+f"(c1), "+f"(c2), "+f"(c3) \
        : "r"(a0), "r"(a1), "r"(a2), "r"(a3), "r"(b0), "r"(b1))

// ================= init: reset barrier + split(hx) =================
__global__ void k_init(const float* __restrict__ hx) {
    int i = blockIdx.x * blockDim.x + threadIdx.x;
    if (i < BB * HH) {
        float v = hx[i];
        __half hh = __float2half(v);
        g_h0h[i] = hh;
        g_h0l[i] = __float2half(v - __half2float(hh));
    }
    if (i == 0) g_barrier = 0u;
}

// ================= build ars =================
__global__ void k_ars(const int* __restrict__ act, const float* __restrict__ rew,
                      const float* __restrict__ stat, const float* __restrict__ emb) {
    int idx = blockIdx.x * blockDim.x + threadIdx.x;
    if (idx >= TT * BB * 32) return;
    int tb = idx >> 5;
    int k = (idx & 31) * 4;
    float4 v;
    if (k < 64) {
        v = *(const float4*)&emb[(size_t)act[tb] * 64 + k];
    } else if (k < 96) {
        float r = rew[tb];
        int ri = (int)floorf((32.0f * (2.0f - r)) / 4.0f);
        int kb = k - 64;
        v.x = (ri == kb    ) ? 1.f : 0.f;
        v.y = (ri == kb + 1) ? 1.f : 0.f;
        v.z = (ri == kb + 2) ? 1.f : 0.f;
        v.w = (ri == kb + 3) ? 1.f : 0.f;
    } else {
        v = *(const float4*)&stat[(size_t)tb * 32 + (k - 96)];
    }
    *(float4*)&g_ars[(size_t)tb * NIN + k] = v;
}

// ================= statsplit: A cols 512..543 = fp16 split(stat) =================
__global__ void k_statsplit(const float* __restrict__ stat) {
    int idx = blockIdx.x * blockDim.x + threadIdx.x;   // over 12800*32
    if (idx >= TT * BB * 32) return;
    int tb = idx >> 5, s = idx & 31;
    float v = stat[(size_t)tb * 32 + s];
    __half hh = __float2half(v);
    __half hl = __float2half(v - __half2float(hh));
    size_t o = (size_t)tb * KP + HH + s;
    g_Ah[o] = hh;
    g_Al[o] = hl;
}

// ================= x_proj (unchanged, known passing; clock diagnostic) ==========
__global__ __launch_bounds__(256, 2) void k_xproj(
    const float* __restrict__ W_ih, const float* __restrict__ b_ih,
    const float* __restrict__ b_hh)
{
    __shared__ __align__(16) float A_s[8][132];
    __shared__ __align__(16) float B2_s[8][264];
    const int tid = threadIdx.x;
    const int g0  = blockIdx.x * 128;
    const int tb0 = blockIdx.y * 128;
    const int tx = tid & 15;
    const int ty = tid >> 4;
    const int mf = tid >> 1;
    const int kf = (tid & 1) * 4;

    ull acc[4][8];
    #pragma unroll
    for (int i = 0; i < 4; i++)
        #pragma unroll
        for (int j = 0; j < 8; j++) acc[i][j] = 0ull;

    float4 rA = *(const float4*)&g_ars[(size_t)(tb0 + mf) * NIN + kf];
    float4 rB = *(const float4*)&W_ih[(size_t)(g0 + mf) * NIN + kf];

    for (int kt = 0; kt < NIN / 8; kt++) {
        A_s[kf + 0][mf] = rA.x; A_s[kf + 1][mf] = rA.y;
        A_s[kf + 2][mf] = rA.z; A_s[kf + 3][mf] = rA.w;
        *(ull*)&B2_s[kf + 0][2 * mf] = pack2(rB.x, rB.x);
        *(ull*)&B2_s[kf + 1][2 * mf] = pack2(rB.y, rB.y);
        *(ull*)&B2_s[kf + 2][2 * mf] = pack2(rB.z, rB.z);
        *(ull*)&B2_s[kf + 3][2 * mf] = pack2(rB.w, rB.w);
        __syncthreads();
        if (kt + 1 < NIN / 8) {
            int k0n = (kt + 1) * 8;
            rA = *(const float4*)&g_ars[(size_t)(tb0 + mf) * NIN + k0n + kf];
            rB = *(const float4*)&W_ih[(size_t)(g0 + mf) * NIN + k0n + kf];
        }
        #pragma unroll
        for (int k = 0; k < 8; k++) {
            ulonglong2 a01 = *(const ulonglong2*)&A_s[k][tx * 8];
            ulonglong2 a23 = *(const ulonglong2*)&A_s[k][tx * 8 + 4];
            ull a[4] = {a01.x, a01.y, a23.x, a23.y};
            #pragma unroll
            for (int jh = 0; jh < 2; jh++) {
                ulonglong2 b01 = *(const ulonglong2*)&B2_s[k][ty * 16 + jh * 8];
                ulonglong2 b23 = *(const ulonglong2*)&B2_s[k][ty * 16 + jh * 8 + 4];
                ull b[4] = {b01.x, b01.y, b23.x, b23.y};
                #pragma unroll
                for (int i = 0; i < 4; i++)
                    #pragma unroll
                    for (int j = 0; j < 4; j++)
                        fma2(acc[i][jh * 4 + j], a[i], b[j]);
            }
        }
        __syncthreads();
    }
    float bs[8];
    #pragma unroll
    for (int j = 0; j < 8; j++) {
        int g = g0 + ty * 8 + j;
        bs[j] = b_ih[g] + b_hh[g];
    }
    #pragma unroll
    for (int rp = 0; rp < 4; rp++) {
        float lo[8], hi[8];
        #pragma unroll
        for (int j = 0; j < 8; j++) {
            float2 c = unpack2(acc[rp][j]);
            lo[j] = c.x + bs[j]; hi[j] = c.y + bs[j];
        }
        int row = tb0 + tx * 8 + rp * 2;
        size_t o0 = (size_t)row * GG + g0 + ty * 8;
        *(float4*)&g_xproj[o0]          = make_float4(lo[0], lo[1], lo[2], lo[3]);
        *(float4*)&g_xproj[o0 + 4]      = make_float4(lo[4], lo[5], lo[6], lo[7]);
        *(float4*)&g_xproj[o0 + GG]     = make_float4(hi[0], hi[1], hi[2], hi[3]);
        *(float4*)&g_xproj[o0 + GG + 4] = make_float4(hi[4], hi[5], hi[6], hi[7]);
    }
}

// ================= persistent LSTM via HMMA (fp16 split h & W, 3 passes) ========
// Grid (64,2) = 128 CTAs: bx -> 8 h-units (32 gate cols), by -> 64 batch rows.
// W_hh slice split-fp16 SMEM-resident; h read from g_Ah/g_Al[t-1] (split written
// by the previous step), staged per step. gates = Ah*Wh + Al*Wh + Ah*Wl.
// 8 warps: warp_m = wid&1 (32 rows), warp_n = wid>>1 (8 gate cols).
__global__ __launch_bounds__(256) void k_lstm_persist(
    const float* __restrict__ W_hh, const float* __restrict__ cx)
{
    extern __shared__ __align__(16) char lsm[];
    __half* Wh = (__half*)lsm + WH_OFF;
    __half* Wl = (__half*)lsm + WL_OFF;
    __half* Hh = (__half*)lsm + HHS_OFF;
    __half* Hl = (__half*)lsm + HLS_OFF;
    float*  gs = (float*)(lsm + GS_BYTE_OFF);
    const uint32_t sWh = smem_u32(Wh), sWl = smem_u32(Wl);
    const uint32_t sHh = smem_u32(Hh), sHl = smem_u32(Hl);

    const int tid = threadIdx.x;
    const int lane = tid & 31;
    const int wid = tid >> 5;
    const int warp_m = wid & 1;
    const int warp_n = wid >> 1;
    const int m0 = blockIdx.x * 8;
    const int r0 = blockIdx.y * 64;

    // ---- one-time: W slice -> split fp16 in SMEM (rows n: gate=n>>3, unit=n&7) --
    #pragma unroll
    for (int it = 0; it < 16; it++) {
        int idx = tid + it * 256;          // 0..4095
        int n = idx >> 7;                  // 0..31
        int k4 = idx & 127;                // float4 along K
        int grow = (n >> 3) * HH + m0 + (n & 7);
        float4 v = *(const float4*)&W_hh[(size_t)grow * HH + k4 * 4];
        __half h0 = __float2half(v.x), h1 = __float2half(v.y);
        __half h2 = __float2half(v.z), h3 = __float2half(v.w);
        int o = n * WS + k4 * 4;
        *(__half2*)&Wh[o]     = __half2(h0, h1);
        *(__half2*)&Wh[o + 2] = __half2(h2, h3);
        *(__half2*)&Wl[o]     = __half2(__float2half(v.x - __half2float(h0)),
                                        __float2half(v.y - __half2float(h1)));
        *(__half2*)&Wl[o + 2] = __half2(__float2half(v.z - __half2float(h2)),
                                        __float2half(v.w - __half2float(h3)));
    }

    // ---- cell state in registers: p = tid*2+e -> r = p>>3, mi = p&7 ----
    float creg[2];
    #pragma unroll
    for (int e = 0; e < 2; e++) {
        int p = tid * 2 + e;
        creg[e] = cx[(size_t)(r0 + (p >> 3)) * HH + m0 + (p & 7)];
    }
    __syncthreads();

    // ldmatrix base addresses (per-thread constant parts)
    const uint32_t bOffN = (uint32_t)((warp_n * 8 + (lane & 7)) * WS
                                      + ((lane >> 3) & 1) * 8) * 2;
    const uint32_t aRow0 = (uint32_t)(warp_m * 32 + (lane & 15));
    const uint32_t aOff0 = (aRow0 * WS + (lane >> 4) * 8) * 2;          // mi=0
    const uint32_t aOff1 = ((aRow0 + 16) * WS + (lane >> 4) * 8) * 2;   // mi=1

    for (int t = 0; t < TT; t++) {
        // prefetch xproj gate terms for the cell update
        float xg[2][4];
        #pragma unroll
        for (int e = 0; e < 2; e++) {
            int p = tid * 2 + e;
            int r = p >> 3, mi = p & 7;
            size_t base = ((size_t)t * BB + r0 + r) * GG + m0 + mi;
            #pragma unroll
            for (int g = 0; g < 4; g++)
                xg[e][g] = g_xproj[base + g * HH];
        }

        // ---- stage h (split fp16) for this step ----
        {
            const __half* srcH; const __half* srcL; int sstr;
            if (t == 0) {
                srcH = g_h0h + (size_t)r0 * HH;
                srcL = g_h0l + (size_t)r0 * HH;
                sstr = HH;
            } else {
                size_t o = ((size_t)(t - 1) * BB + r0) * KP;
                srcH = g_Ah + o;
                srcL = g_Al + o;
                sstr = KP;
            }
            #pragma unroll
            for (int it = 0; it < 16; it++) {
                int idx = tid + it * 256;      // 0..4095
                int r = idx >> 6, c8 = idx & 63;
                *(float4*)&Hh[r * WS + c8 * 8] =
                    *(const float4*)&srcH[(size_t)r * sstr + c8 * 8];
                *(float4*)&Hl[r * WS + c8 * 8] =
                    *(const float4*)&srcL[(size_t)r * sstr + c8 * 8];
            }
        }
        __syncthreads();

        // ---- HMMA: gates(64x32) = h(64x512) . W(32x512)^T, 3 passes ----
        float c0[4], c1[4];
        #pragma unroll
        for (int e = 0; e < 4; e++) { c0[e] = 0.f; c1[e] = 0.f; }

        #pragma unroll 4
        for (int kk = 0; kk < 32; kk++) {
            uint32_t ko = (uint32_t)kk * 32;   // kk*16 halves = 32 bytes
            uint32_t bh0, bh1, bl0, bl1;
            LDSM_X2(bh0, bh1, sWh + bOffN + ko);
            LDSM_X2(bl0, bl1, sWl + bOffN + ko);
            uint32_t ah0[4], ah1[4], al0[4], al1[4];
            LDSM_X4(ah0[0], ah0[1], ah0[2], ah0[3], sHh + aOff0 + ko);
            LDSM_X4(ah1[0], ah1[1], ah1[2], ah1[3], sHh + aOff1 + ko);
            LDSM_X4(al0[0], al0[1], al0[2], al0[3], sHl + aOff0 + ko);
            LDSM_X4(al1[0], al1[1], al1[2], al1[3], sHl + aOff1 + ko);
            MMA16816H(c0[0], c0[1], c0[2], c0[3],
                      ah0[0], ah0[1], ah0[2], ah0[3], bh0, bh1);
            MMA16816H(c1[0], c1[1], c1[2], c1[3],
                      ah1[0], ah1[1], ah1[2], ah1[3], bh0, bh1);
            MMA16816H(c0[0], c0[1], c0[2], c0[3],
                      al0[0], al0[1], al0[2], al0[3], bh0, bh1);
            MMA16816H(c1[0], c1[1], c1[2], c1[3],
                      al1[0], al1[1], al1[2], al1[3], bh0, bh1);
            MMA16816H(c0[0], c0[1], c0[2], c0[3],
                      ah0[0], ah0[1], ah0[2], ah0[3], bl0, bl1);
            MMA16816H(c1[0], c1[1], c1[2], c1[3],
                      ah1[0], ah1[1], ah1[2], ah1[3], bl0, bl1);
        }

        // scatter gate fragments to gs[row][col] (col = gate*8 + unit)
        {
            int row = warp_m * 32 + (lane >> 2);
            int col = warp_n * 8 + (lane & 3) * 2;
            gs[row * 33 + col]            = c0[0];
            gs[row * 33 + col + 1]        = c0[1];
            gs[(row + 8) * 33 + col]      = c0[2];
            gs[(row + 8) * 33 + col + 1]  = c0[3];
            gs[(row + 16) * 33 + col]     = c1[0];
            gs[(row + 16) * 33 + col + 1] = c1[1];
            gs[(row + 24) * 33 + col]     = c1[2];
            gs[(row + 24) * 33 + col + 1] = c1[3];
        }
        __syncthreads();

        // ---- cell update + split-fp16 h write (feeds t+1 recurrence AND k_lin) --
        #pragma unroll
        for (int e = 0; e < 2; e++) {
            int p = tid * 2 + e;
            int r = p >> 3, mi = p & 7;
            float gi = gs[r * 33 + mi]      + xg[e][0];
            float gf = gs[r * 33 + 8 + mi]  + xg[e][1];
            float gg = gs[r * 33 + 16 + mi] + xg[e][2];
            float go = gs[r * 33 + 24 + mi] + xg[e][3];
            float cn = sigf(gf) * creg[e] + sigf(gi) * tanhf(gg);
            float h = sigf(go) * tanhf(cn);
            creg[e] = cn;
            __half hh = __float2half(h);
            __half hl = __float2half(h - __half2float(hh));
            size_t ao = ((size_t)t * BB + r0 + r) * KP + m0 + mi;
            g_Ah[ao] = hh;
            g_Al[ao] = hl;
        }

        // grid barrier (post-spin threadfence keeps cross-CTA g_Ah reads fresh)
        __syncthreads();
        if (tid == 0) {
            __threadfence();
            atomicAdd(&g_barrier, 1u);
            unsigned tgt = (unsigned)(t + 1) * LSTM_CTAS;
            while (*(volatile unsigned*)&g_barrier < tgt) { }
            __threadfence();
        }
        __syncthreads();
    }
}

// ================= fp16 convert of W_lin (single copy) =================
__global__ void k_cvtB(const float* __restrict__ W) {
    int idx = blockIdx.x * blockDim.x + threadIdx.x;   // over NP * (KP/4)
    if (idx >= NP * (KP / 4)) return;
    int row = idx / (KP / 4);
    int c4 = (idx % (KP / 4)) * 4;
    float v[4] = {0.f, 0.f, 0.f, 0.f};
    if (row < NITEMS) {
        #pragma unroll
        for (int j = 0; j < 4; j++) {
            int c = c4 + j;
            if (c < KL) v[j] = W[(size_t)row * KL + c];
        }
    }
    size_t o = (size_t)row * KP + c4;
    *(__half2*)&g_B[o]     = __half2(__float2half(v[0]), __float2half(v[1]));
    *(__half2*)&g_B[o + 2] = __half2(__float2half(v[2]), __float2half(v[3]));
}

// ================= final linear: fp16 split-A x single-B, triple-buffered ======
#define LIN_AT_BYTES (128 * LDS_PAD * 2)   // 10240 per A tile
#define LIN_BT_BYTES (256 * LDS_PAD * 2)   // 20480
#define LIN_STAGE_BYTES (2 * LIN_AT_BYTES + LIN_BT_BYTES)   // 40960
#define LIN_SM_BYTES (3 * LIN_STAGE_BYTES + 256 * 4)

__global__ __launch_bounds__(256) void k_lin_hmma(const float* __restrict__ b_lin,
                                                  float* __restrict__ out)
{
    extern __shared__ __align__(16) char lsm[];
    const uint32_t sb0 = smem_u32(lsm);
    float* bias_s = (float*)(lsm + 3 * LIN_STAGE_BYTES);

    const int tid = threadIdx.x;
    const int lane = tid & 31;
    const int wid = tid >> 5;
    const int warp_m = wid & 1;
    const int warp_n = wid >> 1;
    const int tb0 = blockIdx.x * 128;
    const int v0  = blockIdx.y * 256;

    {
        int v = v0 + tid;
        bias_s[tid] = (v < NITEMS) ? b_lin[v] : 0.f;
    }

    float c[4][8][4];
    #pragma unroll
    for (int mi = 0; mi < 4; mi++)
        #pragma unroll
        for (int ni = 0; ni < 8; ni++)
            #pragma unroll
            for (int e = 0; e < 4; e++) c[mi][ni][e] = 0.f;

    auto load_stage = [&](int s, int d) {
        int kk = s * 32;
        const __half* AhS = g_Ah + (size_t)tb0 * KP + kk;
        const __half* AlS = g_Al + (size_t)tb0 * KP + kk;
        const __half* BS  = g_B  + (size_t)v0  * KP + kk;
        uint32_t ahB = sb0 + d * LIN_STAGE_BYTES;
        uint32_t alB = ahB + LIN_AT_BYTES;
        uint32_t bB  = ahB + 2 * LIN_AT_BYTES;
        #pragma unroll
        for (int it = 0; it < 2; it++) {
            int idx = tid + it * 256;
            int r = idx >> 2, c16 = idx & 3;
            CP_ASYNC16(ahB + (r * LDS_PAD + c16 * 8) * 2,
                       (const char*)(AhS + (size_t)r * KP + c16 * 8));
            CP_ASYNC16(alB + (r * LDS_PAD + c16 * 8) * 2,
                       (const char*)(AlS + (size_t)r * KP + c16 * 8));
        }
        #pragma unroll
        for (int it = 0; it < 4; it++) {
            int idx = tid + it * 256;
            int r = idx >> 2, c16 = idx & 3;
            CP_ASYNC16(bB + (r * LDS_PAD + c16 * 8) * 2,
                       (const char*)(BS + (size_t)r * KP + c16 * 8));
        }
        CP_COMMIT();
    };

    load_stage(0, 0);
    load_stage(1, 1);

    for (int s = 0; s < LIN_STAGES; s++) {
        CP_WAIT(1);
        __syncthreads();
        if (s + 2 < LIN_STAGES) load_stage(s + 2, (s + 2) % 3);

        uint32_t ahB = sb0 + (s % 3) * LIN_STAGE_BYTES;
        uint32_t alB = ahB + LIN_AT_BYTES;
        uint32_t bB  = ahB + 2 * LIN_AT_BYTES;
        #pragma unroll
        for (int ks = 0; ks < 2; ks++) {
            uint32_t b[8][2];
            #pragma unroll
            for (int q = 0; q < 4; q++) {
                int row = warp_n * 64 + q * 16 + (lane & 7) + ((lane >> 4) & 1) * 8;
                int col = ks * 16 + ((lane >> 3) & 1) * 8;
                LDSM_X4(b[2 * q][0], b[2 * q][1], b[2 * q + 1][0], b[2 * q + 1][1],
                        bB + (row * LDS_PAD + col) * 2);
            }
            uint32_t a[4][4];
            #pragma unroll
            for (int mi = 0; mi < 4; mi++) {
                int row = warp_m * 64 + mi * 16 + (lane & 15);
                int col = ks * 16 + (lane >> 4) * 8;
                LDSM_X4(a[mi][0], a[mi][1], a[mi][2], a[mi][3],
                        ahB + (row * LDS_PAD + col) * 2);
            }
            #pragma unroll
            for (int mi = 0; mi < 4; mi++)
                #pragma unroll
                for (int ni = 0; ni < 8; ni++)
                    MMA16816H(c[mi][ni][0], c[mi][ni][1], c[mi][ni][2], c[mi][ni][3],
                              a[mi][0], a[mi][1], a[mi][2], a[mi][3],
                              b[ni][0], b[ni][1]);
            #pragma unroll
            for (int mi = 0; mi < 4; mi++) {
                int row = warp_m * 64 + mi * 16 + (lane & 15);
                int col = ks * 16 + (lane >> 4) * 8;
                LDSM_X4(a[mi][0], a[mi][1], a[mi][2], a[mi][3],
                        alB + (row * LDS_PAD + col) * 2);
            }
            #pragma unroll
            for (int mi = 0; mi < 4; mi++)
                #pragma unroll
                for (int ni = 0; ni < 8; ni++)
                    MMA16816H(c[mi][ni][0], c[mi][ni][1], c[mi][ni][2], c[mi][ni][3],
                              a[mi][0], a[mi][1], a[mi][2], a[mi][3],
                              b[ni][0], b[ni][1]);
        }
        __syncthreads();
    }

    #pragma unroll
    for (int mi = 0; mi < 4; mi++) {
        int m = tb0 + warp_m * 64 + mi * 16 + (lane >> 2);
        #pragma unroll
        for (int ni = 0; ni < 8; ni++) {
            int nl = warp_n * 64 + ni * 8 + (lane & 3) * 2;
            int n = v0 + nl;
            if (n < NITEMS) {
                float b0v = bias_s[nl], b1v = bias_s[nl + 1];
                *(float2*)&out[(size_t)m * NITEMS + n] =
                    make_float2(c[mi][ni][0] + b0v, c[mi][ni][1] + b1v);
                *(float2*)&out[(size_t)(m + 8) * NITEMS + n] =
                    make_float2(c[mi][ni][2] + b0v, c[mi][ni][3] + b1v);
            }
        }
    }
}

// ================= l2 norm =================
__global__ void k_l2zero() { if (threadIdx.x < 2) g_l2[threadIdx.x] = 0.f; }

__global__ void k_l2reduce(const float* __restrict__ W_lin, const float* __restrict__ b_lin) {
    __shared__ float sh[256];
    int tid = threadIdx.x;
    int stride = gridDim.x * blockDim.x;
    float sw = 0.f;
    for (size_t i = blockIdx.x * blockDim.x + tid; i < (size_t)NITEMS * KL; i += stride) {
        float v = W_lin[i]; sw += v * v;
    }
    float sb = 0.f;
    for (int i = blockIdx.x * blockDim.x + tid; i < NITEMS; i += stride) {
        float v = b_lin[i]; sb += v * v;
    }
    sh[tid] = sw; __syncthreads();
    for (int s = 128; s > 0; s >>= 1) { if (tid < s) sh[tid] += sh[tid + s]; __syncthreads(); }
    if (tid == 0) atomicAdd(&g_l2[0], sh[0]);
    __syncthreads();
    sh[tid] = sb; __syncthreads();
    for (int s = 128; s > 0; s >>= 1) { if (tid < s) sh[tid] += sh[tid + s]; __syncthreads(); }
    if (tid == 0) atomicAdd(&g_l2[1], sh[0]);
}

__global__ void k_l2final(float* __restrict__ out, int has_scalar) {
    if (has_scalar && threadIdx.x == 0)
        out[NPN] = sqrtf(g_l2[0]) + sqrtf(g_l2[1]);
}

// ================= launch =================
extern "C" void kernel_launch(void* const* d_in, const int* in_sizes, int n_in,
                              void* d_out, int out_size) {
    const int*   act   = (const int*)  d_in[0];
    const float* rew   = (const float*)d_in[1];
    const float* stat  = (const float*)d_in[2];
    const float* hx    = (const float*)d_in[3];
    const float* cx    = (const float*)d_in[4];
    const float* emb   = (const float*)d_in[5];
    const float* W_ih  = (const float*)d_in[6];
    const float* W_hh  = (const float*)d_in[7];
    const float* b_ih  = (const float*)d_in[8];
    const float* b_hh  = (const float*)d_in[9];
    const float* W_lin = (const float*)d_in[10];
    const float* b_lin = (const float*)d_in[11];
    float* out = (float*)d_out;

    cudaFuncSetAttribute(k_lstm_persist,
                         cudaFuncAttributeMaxDynamicSharedMemorySize, LSTM_SM_BYTES);
    cudaFuncSetAttribute(k_lin_hmma,
                         cudaFuncAttributeMaxDynamicSharedMemorySize, LIN_SM_BYTES);

    k_init<<<(BB * HH + 255) / 256, 256>>>(hx);
    k_ars<<<(TT * BB * 32 + 255) / 256, 256>>>(act, rew, stat, emb);
    k_statsplit<<<(TT * BB * 32 + 255) / 256, 256>>>(stat);
    k_xproj<<<dim3(GG / 128, TT * BB / 128), 256>>>(W_ih, b_ih, b_hh);
    k_cvtB<<<(NP * (KP / 4) + 255) / 256, 256>>>(W_lin);

    // all 100 LSTM steps in one persistent launch (128 CTAs, grid barrier, HMMA)
    k_lstm_persist<<<dim3(64, 2), 256, LSTM_SM_BYTES>>>(W_hh, cx);

    // grid.x = row blocks (fast) so consecutive CTAs share the same B column block
    k_lin_hmma<<<dim3(TT * BB / 128, NP / 256), 256, LIN_SM_BYTES>>>(b_lin, out);

    k_l2zero<<<1, 32>>>();
    k_l2reduce<<<512, 256>>>(W_lin, b_lin);
    k_l2final<<<1, 32>>>(out, out_size > NPN ? 1 : 0);
}

// round 17
// speedup vs baseline: 3.0913x; 1.3040x over previous
#include <cuda_runtime.h>
#include <cuda_fp16.h>
#include <math.h>
#include <stdint.h>

#define TT 100
#define BB 128
#define HH 512
#define GG 2048            // 4*H
#define NIN 128            // rnn input dim
#define NITEMS 10000
#define KL 544             // H + SDIM
#define NPN 128000000      // TT*BB*NITEMS
#define KP 576             // K padded (row stride for split buffers)
#define NP 10240           // items padded to 40*256

// final linear GEMM (fp16 A-hi x fp16 B, single pass)
#define LIN_STAGES 17      // 544/32
#define LDS_PAD 40         // 32 data + 8 pad halves per smem row
#define LIN_AT_BYTES (128 * LDS_PAD * 2)   // 10240
#define LIN_BT_BYTES (256 * LDS_PAD * 2)   // 20480
#define LIN_STAGE_BYTES (LIN_AT_BYTES + LIN_BT_BYTES)       // 30720
#define LIN_SM_BYTES (3 * LIN_STAGE_BYTES + 256 * 4)

// xproj GEMM (split-A x split-B, 3 passes)
#define XP_STAGES 4        // 128/32
#define XP_AT_BYTES (128 * LDS_PAD * 2)    // 10240 each (Ah, Al)
#define XP_BT_BYTES (256 * LDS_PAD * 2)    // 20480 each (Bh, Bl)
#define XP_STAGE_BYTES (2 * XP_AT_BYTES + 2 * XP_BT_BYTES)  // 61440
#define XP_SM_BYTES (3 * XP_STAGE_BYTES + 256 * 4)

// persistent LSTM config (HMMA)
#define LSTM_CTAS 128
#define WS 520             // smem row stride in halves
#define WH_OFF 0
#define WL_OFF 16640
#define HHS_OFF 33280
#define HLS_OFF 66560
#define GS_BYTE_OFF 199680
#define LSTM_SM_BYTES 208128

typedef unsigned long long ull;

// ---------------- static device scratch (no runtime allocation) ----------------
__device__ float g_xproj[TT * BB * GG];
__device__ float g_l2[2];
__device__ unsigned g_barrier;
__device__ __half g_Ah[(size_t)TT * BB * KP];   // fp16 hi(h | stat) per t
__device__ __half g_Al[(size_t)TT * BB * KP];   // fp16 lo (used by LSTM recurrence)
__device__ __half g_B[(size_t)NP * KP];         // fp16 W_lin
__device__ __half g_h0h[BB * HH];               // split(hx) hi
__device__ __half g_h0l[BB * HH];               // split(hx) lo
__device__ __half g_arsh[(size_t)TT * BB * NIN]; // split(ars) hi
__device__ __half g_arsl[(size_t)TT * BB * NIN]; // split(ars) lo
__device__ __half g_Wih_h[(size_t)GG * NIN];     // split(W_ih) hi
__device__ __half g_Wih_l[(size_t)GG * NIN];     // split(W_ih) lo

__device__ __forceinline__ float sigf(float x) { return 1.0f / (1.0f + expf(-x)); }

__device__ __forceinline__ uint32_t smem_u32(const void* p) {
    uint32_t a;
    asm("{ .reg .u64 t; cvta.to.shared.u64 t, %1; cvt.u32.u64 %0, t; }" : "=r"(a) : "l"(p));
    return a;
}

// ---------------- cp.async / ldmatrix / mma (baseline sm_80 PTX) ----------------
#define CP_ASYNC16(sdst, gsrc) \
    asm volatile("cp.async.cg.shared.global [%0], [%1], 16;" :: "r"(sdst), "l"(gsrc))
#define CP_COMMIT() asm volatile("cp.async.commit_group;" ::: "memory")
#define CP_WAIT(n)  asm volatile("cp.async.wait_group %0;" :: "n"(n) : "memory")

#define LDSM_X4(r0, r1, r2, r3, addr) \
    asm volatile("ldmatrix.sync.aligned.m8n8.x4.shared.b16 {%0,%1,%2,%3}, [%4];" \
        : "=r"(r0), "=r"(r1), "=r"(r2), "=r"(r3) : "r"(addr))
#define LDSM_X2(r0, r1, addr) \
    asm volatile("ldmatrix.sync.aligned.m8n8.x2.shared.b16 {%0,%1}, [%2];" \
        : "=r"(r0), "=r"(r1) : "r"(addr))

#define MMA16816H(c0, c1, c2, c3, a0, a1, a2, a3, b0, b1) \
    asm volatile("mma.sync.aligned.m16n8k16.row.col.f32.f16.f16.f32 " \
        "{%0,%1,%2,%3}, {%4,%5,%6,%7}, {%8,%9}, {%0,%1,%2,%3};" \
        : "+f"(c0), "+f"(c1), "+f"(c2), "+f"(c3) \
        : "r"(a0), "r"(a1), "r"(a2), "r"(a3), "r"(b0), "r"(b1))

// ================= init: reset barrier + split(hx) =================
__global__ void k_init(const float* __restrict__ hx) {
    int i = blockIdx.x * blockDim.x + threadIdx.x;
    if (i < BB * HH) {
        float v = hx[i];
        __half hh = __float2half(v);
        g_h0h[i] = hh;
        g_h0l[i] = __float2half(v - __half2float(hh));
    }
    if (i == 0) g_barrier = 0u;
}

// ================= build ars directly as split fp16 =================
__global__ void k_arssplit(const int* __restrict__ act, const float* __restrict__ rew,
                           const float* __restrict__ stat, const float* __restrict__ emb) {
    int idx = blockIdx.x * blockDim.x + threadIdx.x;   // over 12800*32 float4s
    if (idx >= TT * BB * 32) return;
    int tb = idx >> 5;
    int k = (idx & 31) * 4;
    float4 v;
    if (k < 64) {
        v = *(const float4*)&emb[(size_t)act[tb] * 64 + k];
    } else if (k < 96) {
        float r = rew[tb];
        int ri = (int)floorf((32.0f * (2.0f - r)) / 4.0f);
        int kb = k - 64;
        v.x = (ri == kb    ) ? 1.f : 0.f;
        v.y = (ri == kb + 1) ? 1.f : 0.f;
        v.z = (ri == kb + 2) ? 1.f : 0.f;
        v.w = (ri == kb + 3) ? 1.f : 0.f;
    } else {
        v = *(const float4*)&stat[(size_t)tb * 32 + (k - 96)];
    }
    __half h0 = __float2half(v.x), h1 = __float2half(v.y);
    __half h2 = __float2half(v.z), h3 = __float2half(v.w);
    size_t o = (size_t)tb * NIN + k;
    *(__half2*)&g_arsh[o]     = __half2(h0, h1);
    *(__half2*)&g_arsh[o + 2] = __half2(h2, h3);
    *(__half2*)&g_arsl[o]     = __half2(__float2half(v.x - __half2float(h0)),
                                        __float2half(v.y - __half2float(h1)));
    *(__half2*)&g_arsl[o + 2] = __half2(__float2half(v.z - __half2float(h2)),
                                        __float2half(v.w - __half2float(h3)));
}

// ================= statsplit: A cols 512..543 = fp16 split(stat) =================
__global__ void k_statsplit(const float* __restrict__ stat) {
    int idx = blockIdx.x * blockDim.x + threadIdx.x;   // over 12800*32
    if (idx >= TT * BB * 32) return;
    int tb = idx >> 5, s = idx & 31;
    float v = stat[(size_t)tb * 32 + s];
    __half hh = __float2half(v);
    __half hl = __float2half(v - __half2float(hh));
    size_t o = (size_t)tb * KP + HH + s;
    g_Ah[o] = hh;
    g_Al[o] = hl;
}

// ================= W_ih split fp16 =================
__global__ void k_cvtW(const float* __restrict__ W) {
    int idx = blockIdx.x * blockDim.x + threadIdx.x;   // over GG*(NIN/4)
    if (idx >= GG * (NIN / 4)) return;
    int row = idx >> 5;
    int c4 = (idx & 31) * 4;
    float4 v = *(const float4*)&W[(size_t)row * NIN + c4];
    __half h0 = __float2half(v.x), h1 = __float2half(v.y);
    __half h2 = __float2half(v.z), h3 = __float2half(v.w);
    size_t o = (size_t)row * NIN + c4;
    *(__half2*)&g_Wih_h[o]     = __half2(h0, h1);
    *(__half2*)&g_Wih_h[o + 2] = __half2(h2, h3);
    *(__half2*)&g_Wih_l[o]     = __half2(__float2half(v.x - __half2float(h0)),
                                         __float2half(v.y - __half2float(h1)));
    *(__half2*)&g_Wih_l[o + 2] = __half2(__float2half(v.z - __half2float(h2)),
                                         __float2half(v.w - __half2float(h3)));
}

// ================= x_proj via HMMA: split-A x split-B, 3 passes =================
// CTA 128x256, 8 warps (2x4), warp tile 64x64. K=128 in 4 stages of 32.
// gates = Ah*Wh + Al*Wh + Ah*Wl (+ b_ih + b_hh), fp32 out to g_xproj.
__global__ __launch_bounds__(256) void k_xproj_hmma(
    const float* __restrict__ b_ih, const float* __restrict__ b_hh)
{
    extern __shared__ __align__(16) char lsm[];
    const uint32_t sb0 = smem_u32(lsm);
    float* bias_s = (float*)(lsm + 3 * XP_STAGE_BYTES);

    const int tid = threadIdx.x;
    const int lane = tid & 31;
    const int wid = tid >> 5;
    const int warp_m = wid & 1;
    const int warp_n = wid >> 1;
    const int tb0 = blockIdx.x * 128;
    const int g0  = blockIdx.y * 256;

    {
        int g = g0 + tid;
        bias_s[tid] = b_ih[g] + b_hh[g];
    }

    float c[4][8][4];
    #pragma unroll
    for (int mi = 0; mi < 4; mi++)
        #pragma unroll
        for (int ni = 0; ni < 8; ni++)
            #pragma unroll
            for (int e = 0; e < 4; e++) c[mi][ni][e] = 0.f;

    auto load_stage = [&](int s, int d) {
        int kk = s * 32;
        const __half* AhS = g_arsh + (size_t)tb0 * NIN + kk;
        const __half* AlS = g_arsl + (size_t)tb0 * NIN + kk;
        const __half* BhS = g_Wih_h + (size_t)g0 * NIN + kk;
        const __half* BlS = g_Wih_l + (size_t)g0 * NIN + kk;
        uint32_t ahB = sb0 + d * XP_STAGE_BYTES;
        uint32_t alB = ahB + XP_AT_BYTES;
        uint32_t bhB = ahB + 2 * XP_AT_BYTES;
        uint32_t blB = bhB + XP_BT_BYTES;
        #pragma unroll
        for (int it = 0; it < 2; it++) {           // A tiles: 512 chunks each
            int idx = tid + it * 256;
            int r = idx >> 2, c16 = idx & 3;
            CP_ASYNC16(ahB + (r * LDS_PAD + c16 * 8) * 2,
                       (const char*)(AhS + (size_t)r * NIN + c16 * 8));
            CP_ASYNC16(alB + (r * LDS_PAD + c16 * 8) * 2,
                       (const char*)(AlS + (size_t)r * NIN + c16 * 8));
        }
        #pragma unroll
        for (int it = 0; it < 4; it++) {           // B tiles: 1024 chunks each
            int idx = tid + it * 256;
            int r = idx >> 2, c16 = idx & 3;
            CP_ASYNC16(bhB + (r * LDS_PAD + c16 * 8) * 2,
                       (const char*)(BhS + (size_t)r * NIN + c16 * 8));
            CP_ASYNC16(blB + (r * LDS_PAD + c16 * 8) * 2,
                       (const char*)(BlS + (size_t)r * NIN + c16 * 8));
        }
        CP_COMMIT();
    };

    load_stage(0, 0);
    load_stage(1, 1);

    for (int s = 0; s < XP_STAGES; s++) {
        if (s + 2 < XP_STAGES) { CP_WAIT(1); } else { CP_WAIT(0); }
        __syncthreads();
        if (s + 2 < XP_STAGES) load_stage(s + 2, (s + 2) % 3);

        uint32_t ahB = sb0 + (s % 3) * XP_STAGE_BYTES;
        uint32_t alB = ahB + XP_AT_BYTES;
        uint32_t bhB = ahB + 2 * XP_AT_BYTES;
        uint32_t blB = bhB + XP_BT_BYTES;
        #pragma unroll
        for (int ks = 0; ks < 2; ks++) {
            uint32_t b[8][2], a[4][4];
            // pass 1+2: Bh with Ah then Al
            #pragma unroll
            for (int q = 0; q < 4; q++) {
                int row = warp_n * 64 + q * 16 + (lane & 7) + ((lane >> 4) & 1) * 8;
                int col = ks * 16 + ((lane >> 3) & 1) * 8;
                LDSM_X4(b[2 * q][0], b[2 * q][1], b[2 * q + 1][0], b[2 * q + 1][1],
                        bhB + (row * LDS_PAD + col) * 2);
            }
            #pragma unroll
            for (int mi = 0; mi < 4; mi++) {
                int row = warp_m * 64 + mi * 16 + (lane & 15);
                int col = ks * 16 + (lane >> 4) * 8;
                LDSM_X4(a[mi][0], a[mi][1], a[mi][2], a[mi][3],
                        ahB + (row * LDS_PAD + col) * 2);
            }
            #pragma unroll
            for (int mi = 0; mi < 4; mi++)
                #pragma unroll
                for (int ni = 0; ni < 8; ni++)
                    MMA16816H(c[mi][ni][0], c[mi][ni][1], c[mi][ni][2], c[mi][ni][3],
                              a[mi][0], a[mi][1], a[mi][2], a[mi][3],
                              b[ni][0], b[ni][1]);
            #pragma unroll
            for (int mi = 0; mi < 4; mi++) {
                int row = warp_m * 64 + mi * 16 + (lane & 15);
                int col = ks * 16 + (lane >> 4) * 8;
                LDSM_X4(a[mi][0], a[mi][1], a[mi][2], a[mi][3],
                        alB + (row * LDS_PAD + col) * 2);
            }
            #pragma unroll
            for (int mi = 0; mi < 4; mi++)
                #pragma unroll
                for (int ni = 0; ni < 8; ni++)
                    MMA16816H(c[mi][ni][0], c[mi][ni][1], c[mi][ni][2], c[mi][ni][3],
                              a[mi][0], a[mi][1], a[mi][2], a[mi][3],
                              b[ni][0], b[ni][1]);
            // pass 3: Bl with Ah
            #pragma unroll
            for (int q = 0; q < 4; q++) {
                int row = warp_n * 64 + q * 16 + (lane & 7) + ((lane >> 4) & 1) * 8;
                int col = ks * 16 + ((lane >> 3) & 1) * 8;
                LDSM_X4(b[2 * q][0], b[2 * q][1], b[2 * q + 1][0], b[2 * q + 1][1],
                        blB + (row * LDS_PAD + col) * 2);
            }
            #pragma unroll
            for (int mi = 0; mi < 4; mi++) {
                int row = warp_m * 64 + mi * 16 + (lane & 15);
                int col = ks * 16 + (lane >> 4) * 8;
                LDSM_X4(a[mi][0], a[mi][1], a[mi][2], a[mi][3],
                        ahB + (row * LDS_PAD + col) * 2);
            }
            #pragma unroll
            for (int mi = 0; mi < 4; mi++)
                #pragma unroll
                for (int ni = 0; ni < 8; ni++)
                    MMA16816H(c[mi][ni][0], c[mi][ni][1], c[mi][ni][2], c[mi][ni][3],
                              a[mi][0], a[mi][1], a[mi][2], a[mi][3],
                              b[ni][0], b[ni][1]);
        }
    }

    // epilogue: fp32 to g_xproj with bias; N=2048 exact, no guards
    #pragma unroll
    for (int mi = 0; mi < 4; mi++) {
        int m = tb0 + warp_m * 64 + mi * 16 + (lane >> 2);
        #pragma unroll
        for (int ni = 0; ni < 8; ni++) {
            int nl = warp_n * 64 + ni * 8 + (lane & 3) * 2;
            float b0v = bias_s[nl], b1v = bias_s[nl + 1];
            size_t o = (size_t)m * GG + g0 + nl;
            *(float2*)&g_xproj[o] =
                make_float2(c[mi][ni][0] + b0v, c[mi][ni][1] + b1v);
            *(float2*)&g_xproj[o + 8 * GG] =
                make_float2(c[mi][ni][2] + b0v, c[mi][ni][3] + b1v);
        }
    }
}

// ================= persistent LSTM via HMMA (unchanged from R16) ================
__global__ __launch_bounds__(256) void k_lstm_persist(
    const float* __restrict__ W_hh, const float* __restrict__ cx)
{
    extern __shared__ __align__(16) char lsm[];
    __half* Wh = (__half*)lsm + WH_OFF;
    __half* Wl = (__half*)lsm + WL_OFF;
    __half* Hh = (__half*)lsm + HHS_OFF;
    __half* Hl = (__half*)lsm + HLS_OFF;
    float*  gs = (float*)(lsm + GS_BYTE_OFF);
    const uint32_t sWh = smem_u32(Wh), sWl = smem_u32(Wl);
    const uint32_t sHh = smem_u32(Hh), sHl = smem_u32(Hl);

    const int tid = threadIdx.x;
    const int lane = tid & 31;
    const int wid = tid >> 5;
    const int warp_m = wid & 1;
    const int warp_n = wid >> 1;
    const int m0 = blockIdx.x * 8;
    const int r0 = blockIdx.y * 64;

    #pragma unroll
    for (int it = 0; it < 16; it++) {
        int idx = tid + it * 256;
        int n = idx >> 7;
        int k4 = idx & 127;
        int grow = (n >> 3) * HH + m0 + (n & 7);
        float4 v = *(const float4*)&W_hh[(size_t)grow * HH + k4 * 4];
        __half h0 = __float2half(v.x), h1 = __float2half(v.y);
        __half h2 = __float2half(v.z), h3 = __float2half(v.w);
        int o = n * WS + k4 * 4;
        *(__half2*)&Wh[o]     = __half2(h0, h1);
        *(__half2*)&Wh[o + 2] = __half2(h2, h3);
        *(__half2*)&Wl[o]     = __half2(__float2half(v.x - __half2float(h0)),
                                        __float2half(v.y - __half2float(h1)));
        *(__half2*)&Wl[o + 2] = __half2(__float2half(v.z - __half2float(h2)),
                                        __float2half(v.w - __half2float(h3)));
    }

    float creg[2];
    #pragma unroll
    for (int e = 0; e < 2; e++) {
        int p = tid * 2 + e;
        creg[e] = cx[(size_t)(r0 + (p >> 3)) * HH + m0 + (p & 7)];
    }
    __syncthreads();

    const uint32_t bOffN = (uint32_t)((warp_n * 8 + (lane & 7)) * WS
                                      + ((lane >> 3) & 1) * 8) * 2;
    const uint32_t aRow0 = (uint32_t)(warp_m * 32 + (lane & 15));
    const uint32_t aOff0 = (aRow0 * WS + (lane >> 4) * 8) * 2;
    const uint32_t aOff1 = ((aRow0 + 16) * WS + (lane >> 4) * 8) * 2;

    for (int t = 0; t < TT; t++) {
        float xg[2][4];
        #pragma unroll
        for (int e = 0; e < 2; e++) {
            int p = tid * 2 + e;
            int r = p >> 3, mi = p & 7;
            size_t base = ((size_t)t * BB + r0 + r) * GG + m0 + mi;
            #pragma unroll
            for (int g = 0; g < 4; g++)
                xg[e][g] = g_xproj[base + g * HH];
        }

        {
            const __half* srcH; const __half* srcL; int sstr;
            if (t == 0) {
                srcH = g_h0h + (size_t)r0 * HH;
                srcL = g_h0l + (size_t)r0 * HH;
                sstr = HH;
            } else {
                size_t o = ((size_t)(t - 1) * BB + r0) * KP;
                srcH = g_Ah + o;
                srcL = g_Al + o;
                sstr = KP;
            }
            #pragma unroll
            for (int it = 0; it < 16; it++) {
                int idx = tid + it * 256;
                int r = idx >> 6, c8 = idx & 63;
                *(float4*)&Hh[r * WS + c8 * 8] =
                    *(const float4*)&srcH[(size_t)r * sstr + c8 * 8];
                *(float4*)&Hl[r * WS + c8 * 8] =
                    *(const float4*)&srcL[(size_t)r * sstr + c8 * 8];
            }
        }
        __syncthreads();

        float c0[4], c1[4];
        #pragma unroll
        for (int e = 0; e < 4; e++) { c0[e] = 0.f; c1[e] = 0.f; }

        #pragma unroll 4
        for (int kk = 0; kk < 32; kk++) {
            uint32_t ko = (uint32_t)kk * 32;
            uint32_t bh0, bh1, bl0, bl1;
            LDSM_X2(bh0, bh1, sWh + bOffN + ko);
            LDSM_X2(bl0, bl1, sWl + bOffN + ko);
            uint32_t ah0[4], ah1[4], al0[4], al1[4];
            LDSM_X4(ah0[0], ah0[1], ah0[2], ah0[3], sHh + aOff0 + ko);
            LDSM_X4(ah1[0], ah1[1], ah1[2], ah1[3], sHh + aOff1 + ko);
            LDSM_X4(al0[0], al0[1], al0[2], al0[3], sHl + aOff0 + ko);
            LDSM_X4(al1[0], al1[1], al1[2], al1[3], sHl + aOff1 + ko);
            MMA16816H(c0[0], c0[1], c0[2], c0[3],
                      ah0[0], ah0[1], ah0[2], ah0[3], bh0, bh1);
            MMA16816H(c1[0], c1[1], c1[2], c1[3],
                      ah1[0], ah1[1], ah1[2], ah1[3], bh0, bh1);
            MMA16816H(c0[0], c0[1], c0[2], c0[3],
                      al0[0], al0[1], al0[2], al0[3], bh0, bh1);
            MMA16816H(c1[0], c1[1], c1[2], c1[3],
                      al1[0], al1[1], al1[2], al1[3], bh0, bh1);
            MMA16816H(c0[0], c0[1], c0[2], c0[3],
                      ah0[0], ah0[1], ah0[2], ah0[3], bl0, bl1);
            MMA16816H(c1[0], c1[1], c1[2], c1[3],
                      ah1[0], ah1[1], ah1[2], ah1[3], bl0, bl1);
        }

        {
            int row = warp_m * 32 + (lane >> 2);
            int col = warp_n * 8 + (lane & 3) * 2;
            gs[row * 33 + col]            = c0[0];
            gs[row * 33 + col + 1]        = c0[1];
            gs[(row + 8) * 33 + col]      = c0[2];
            gs[(row + 8) * 33 + col + 1]  = c0[3];
            gs[(row + 16) * 33 + col]     = c1[0];
            gs[(row + 16) * 33 + col + 1] = c1[1];
            gs[(row + 24) * 33 + col]     = c1[2];
            gs[(row + 24) * 33 + col + 1] = c1[3];
        }
        __syncthreads();

        #pragma unroll
        for (int e = 0; e < 2; e++) {
            int p = tid * 2 + e;
            int r = p >> 3, mi = p & 7;
            float gi = gs[r * 33 + mi]      + xg[e][0];
            float gf = gs[r * 33 + 8 + mi]  + xg[e][1];
            float gg = gs[r * 33 + 16 + mi] + xg[e][2];
            float go = gs[r * 33 + 24 + mi] + xg[e][3];
            float cn = sigf(gf) * creg[e] + sigf(gi) * tanhf(gg);
            float h = sigf(go) * tanhf(cn);
            creg[e] = cn;
            __half hh = __float2half(h);
            __half hl = __float2half(h - __half2float(hh));
            size_t ao = ((size_t)t * BB + r0 + r) * KP + m0 + mi;
            g_Ah[ao] = hh;
            g_Al[ao] = hl;
        }

        __syncthreads();
        if (tid == 0) {
            __threadfence();
            atomicAdd(&g_barrier, 1u);
            unsigned tgt = (unsigned)(t + 1) * LSTM_CTAS;
            while (*(volatile unsigned*)&g_barrier < tgt) { }
            __threadfence();
        }
        __syncthreads();
    }
}

// ================= fp16 convert of W_lin =================
__global__ void k_cvtB(const float* __restrict__ W) {
    int idx = blockIdx.x * blockDim.x + threadIdx.x;   // over NP * (KP/4)
    if (idx >= NP * (KP / 4)) return;
    int row = idx / (KP / 4);
    int c4 = (idx % (KP / 4)) * 4;
    float v[4] = {0.f, 0.f, 0.f, 0.f};
    if (row < NITEMS) {
        #pragma unroll
        for (int j = 0; j < 4; j++) {
            int c = c4 + j;
            if (c < KL) v[j] = W[(size_t)row * KL + c];
        }
    }
    size_t o = (size_t)row * KP + c4;
    *(__half2*)&g_B[o]     = __half2(__float2half(v[0]), __float2half(v[1]));
    *(__half2*)&g_B[o + 2] = __half2(__float2half(v[2]), __float2half(v[3]));
}

// ================= final linear: fp16 A-hi x B, single pass, triple-buffered ====
__global__ __launch_bounds__(256) void k_lin_hmma(const float* __restrict__ b_lin,
                                                  float* __restrict__ out)
{
    extern __shared__ __align__(16) char lsm[];
    const uint32_t sb0 = smem_u32(lsm);
    float* bias_s = (float*)(lsm + 3 * LIN_STAGE_BYTES);

    const int tid = threadIdx.x;
    const int lane = tid & 31;
    const int wid = tid >> 5;
    const int warp_m = wid & 1;
    const int warp_n = wid >> 1;
    const int tb0 = blockIdx.x * 128;
    const int v0  = blockIdx.y * 256;

    {
        int v = v0 + tid;
        bias_s[tid] = (v < NITEMS) ? b_lin[v] : 0.f;
    }

    float c[4][8][4];
    #pragma unroll
    for (int mi = 0; mi < 4; mi++)
        #pragma unroll
        for (int ni = 0; ni < 8; ni++)
            #pragma unroll
            for (int e = 0; e < 4; e++) c[mi][ni][e] = 0.f;

    auto load_stage = [&](int s, int d) {
        int kk = s * 32;
        const __half* AhS = g_Ah + (size_t)tb0 * KP + kk;
        const __half* BS  = g_B  + (size_t)v0  * KP + kk;
        uint32_t ahB = sb0 + d * LIN_STAGE_BYTES;
        uint32_t bB  = ahB + LIN_AT_BYTES;
        #pragma unroll
        for (int it = 0; it < 2; it++) {
            int idx = tid + it * 256;
            int r = idx >> 2, c16 = idx & 3;
            CP_ASYNC16(ahB + (r * LDS_PAD + c16 * 8) * 2,
                       (const char*)(AhS + (size_t)r * KP + c16 * 8));
        }
        #pragma unroll
        for (int it = 0; it < 4; it++) {
            int idx = tid + it * 256;
            int r = idx >> 2, c16 = idx & 3;
            CP_ASYNC16(bB + (r * LDS_PAD + c16 * 8) * 2,
                       (const char*)(BS + (size_t)r * KP + c16 * 8));
        }
        CP_COMMIT();
    };

    load_stage(0, 0);
    load_stage(1, 1);

    for (int s = 0; s < LIN_STAGES; s++) {
        if (s + 2 < LIN_STAGES) { CP_WAIT(1); } else { CP_WAIT(0); }
        __syncthreads();
        if (s + 2 < LIN_STAGES) load_stage(s + 2, (s + 2) % 3);

        uint32_t ahB = sb0 + (s % 3) * LIN_STAGE_BYTES;
        uint32_t bB  = ahB + LIN_AT_BYTES;
        #pragma unroll
        for (int ks = 0; ks < 2; ks++) {
            uint32_t b[8][2], a[4][4];
            #pragma unroll
            for (int q = 0; q < 4; q++) {
                int row = warp_n * 64 + q * 16 + (lane & 7) + ((lane >> 4) & 1) * 8;
                int col = ks * 16 + ((lane >> 3) & 1) * 8;
                LDSM_X4(b[2 * q][0], b[2 * q][1], b[2 * q + 1][0], b[2 * q + 1][1],
                        bB + (row * LDS_PAD + col) * 2);
            }
            #pragma unroll
            for (int mi = 0; mi < 4; mi++) {
                int row = warp_m * 64 + mi * 16 + (lane & 15);
                int col = ks * 16 + (lane >> 4) * 8;
                LDSM_X4(a[mi][0], a[mi][1], a[mi][2], a[mi][3],
                        ahB + (row * LDS_PAD + col) * 2);
            }
            #pragma unroll
            for (int mi = 0; mi < 4; mi++)
                #pragma unroll
                for (int ni = 0; ni < 8; ni++)
                    MMA16816H(c[mi][ni][0], c[mi][ni][1], c[mi][ni][2], c[mi][ni][3],
                              a[mi][0], a[mi][1], a[mi][2], a[mi][3],
                              b[ni][0], b[ni][1]);
        }
    }

    #pragma unroll
    for (int mi = 0; mi < 4; mi++) {
        int m = tb0 + warp_m * 64 + mi * 16 + (lane >> 2);
        #pragma unroll
        for (int ni = 0; ni < 8; ni++) {
            int nl = warp_n * 64 + ni * 8 + (lane & 3) * 2;
            int n = v0 + nl;
            if (n < NITEMS) {
                float b0v = bias_s[nl], b1v = bias_s[nl + 1];
                *(float2*)&out[(size_t)m * NITEMS + n] =
                    make_float2(c[mi][ni][0] + b0v, c[mi][ni][1] + b1v);
                *(float2*)&out[(size_t)(m + 8) * NITEMS + n] =
                    make_float2(c[mi][ni][2] + b0v, c[mi][ni][3] + b1v);
            }
        }
    }
}

// ================= l2 norm =================
__global__ void k_l2zero() { if (threadIdx.x < 2) g_l2[threadIdx.x] = 0.f; }

__global__ void k_l2reduce(const float* __restrict__ W_lin, const float* __restrict__ b_lin) {
    __shared__ float sh[256];
    int tid = threadIdx.x;
    int stride = gridDim.x * blockDim.x;
    float sw = 0.f;
    for (size_t i = blockIdx.x * blockDim.x + tid; i < (size_t)NITEMS * KL; i += stride) {
        float v = W_lin[i]; sw += v * v;
    }
    float sb = 0.f;
    for (int i = blockIdx.x * blockDim.x + tid; i < NITEMS; i += stride) {
        float v = b_lin[i]; sb += v * v;
    }
    sh[tid] = sw; __syncthreads();
    for (int s = 128; s > 0; s >>= 1) { if (tid < s) sh[tid] += sh[tid + s]; __syncthreads(); }
    if (tid == 0) atomicAdd(&g_l2[0], sh[0]);
    __syncthreads();
    sh[tid] = sb; __syncthreads();
    for (int s = 128; s > 0; s >>= 1) { if (tid < s) sh[tid] += sh[tid + s]; __syncthreads(); }
    if (tid == 0) atomicAdd(&g_l2[1], sh[0]);
}

__global__ void k_l2final(float* __restrict__ out, int has_scalar) {
    if (has_scalar && threadIdx.x == 0)
        out[NPN] = sqrtf(g_l2[0]) + sqrtf(g_l2[1]);
}

// ================= launch =================
extern "C" void kernel_launch(void* const* d_in, const int* in_sizes, int n_in,
                              void* d_out, int out_size) {
    const int*   act   = (const int*)  d_in[0];
    const float* rew   = (const float*)d_in[1];
    const float* stat  = (const float*)d_in[2];
    const float* hx    = (const float*)d_in[3];
    const float* cx    = (const float*)d_in[4];
    const float* emb   = (const float*)d_in[5];
    const float* W_ih  = (const float*)d_in[6];
    const float* W_hh  = (const float*)d_in[7];
    const float* b_ih  = (const float*)d_in[8];
    const float* b_hh  = (const float*)d_in[9];
    const float* W_lin = (const float*)d_in[10];
    const float* b_lin = (const float*)d_in[11];
    float* out = (float*)d_out;

    cudaFuncSetAttribute(k_lstm_persist,
                         cudaFuncAttributeMaxDynamicSharedMemorySize, LSTM_SM_BYTES);
    cudaFuncSetAttribute(k_lin_hmma,
                         cudaFuncAttributeMaxDynamicSharedMemorySize, LIN_SM_BYTES);
    cudaFuncSetAttribute(k_xproj_hmma,
                         cudaFuncAttributeMaxDynamicSharedMemorySize, XP_SM_BYTES);

    k_init<<<(BB * HH + 255) / 256, 256>>>(hx);
    k_arssplit<<<(TT * BB * 32 + 255) / 256, 256>>>(act, rew, stat, emb);
    k_statsplit<<<(TT * BB * 32 + 255) / 256, 256>>>(stat);
    k_cvtW<<<(GG * (NIN / 4) + 255) / 256, 256>>>(W_ih);
    k_cvtB<<<(NP * (KP / 4) + 255) / 256, 256>>>(W_lin);

    // x-projection GEMM on tensor cores (3-pass split)
    k_xproj_hmma<<<dim3(TT * BB / 128, GG / 256), 256, XP_SM_BYTES>>>(b_ih, b_hh);

    // all 100 LSTM steps in one persistent launch (128 CTAs, grid barrier, HMMA)
    k_lstm_persist<<<dim3(64, 2), 256, LSTM_SM_BYTES>>>(W_hh, cx);

    // final linear (single-pass fp16), row blocks fast for B L2 reuse
    k_lin_hmma<<<dim3(TT * BB / 128, NP / 256), 256, LIN_SM_BYTES>>>(b_lin, out);

    k_l2zero<<<1, 32>>>();
    k_l2reduce<<<512, 256>>>(W_lin, b_lin);
    k_l2final<<<1, 32>>>(out, out_size > NPN ? 1 : 0);
}